// round 13
// baseline (speedup 1.0000x reference)
#include <cuda_runtime.h>
#include <cstdint>

#if defined(__CUDA_ARCH_FEAT_SM103_ALL) || defined(__CUDA_ARCH_FEAT_SM100_ALL) || \
    (defined(__CUDA_ARCH_FAMILY_SPECIFIC__) && (__CUDA_ARCH_FAMILY_SPECIFIC__ >= 1000))
#define TC_OK 1
#else
#define TC_OK 0
#endif

#define NTOK 4096
#define C_DIM 3072
#define F_DIM 12288
#define NB 32
#define BM_ 128
#define MBM_ 16
#define MBS 256
#define KSEL 1536

#define IDESC_TF32 ((1u<<4)|(2u<<7)|(2u<<10)|(16u<<17)|(8u<<24))
#define SWZ(o) ((o) ^ (((o) >> 3) & 0x70))

#define SEL_SMEM (8 * 16384 + 1024)
#define G_SMEM   (3 * 32768 + 1024)    // 3 stages x (A 16KB + B 16KB); 6 half-slots

// ---------------- scratch ----------------
__device__ float g_bmx[MBS * C_DIM];
__device__ float g_mdiff[NB * F_DIM];
__device__ int   g_inds[NB * KSEL];
__device__ float g_delta[(size_t)NB * BM_ * KSEL];   // [blk][tok][ch], tf32-RNA rounded
__device__ float g_xr[(size_t)NTOK * C_DIM];         // x pre-rounded to tf32-RNA

// ---------------- common helpers ----------------
__device__ __forceinline__ uint32_t f2tf(float x) {
    uint32_t u; asm("cvt.rna.tf32.f32 %0, %1;" : "=r"(u) : "f"(x)); return u;
}
__device__ __forceinline__ float gelu_t(float v) {
    return 0.5f * v * (1.f + tanhf(0.7978845608028654f * (v + 0.044715f * v * v * v)));
}
__device__ __forceinline__ void mma_frag(float c[4], const uint32_t a[4], const uint32_t b[2]) {
    asm volatile(
        "mma.sync.aligned.m16n8k8.row.col.f32.tf32.tf32.f32 "
        "{%0,%1,%2,%3},{%4,%5,%6,%7},{%8,%9},{%0,%1,%2,%3};"
        : "+f"(c[0]), "+f"(c[1]), "+f"(c[2]), "+f"(c[3])
        : "r"(a[0]), "r"(a[1]), "r"(a[2]), "r"(a[3]), "r"(b[0]), "r"(b[1]));
}

#if TC_OK
__device__ __forceinline__ uint32_t sm32(const void* p) {
    uint32_t a;
    asm("{ .reg .u64 t; cvta.to.shared.u64 t, %1; cvt.u32.u64 %0, t; }" : "=r"(a) : "l"(p));
    return a;
}
__device__ __forceinline__ void mbar_init(uint32_t m, uint32_t c) {
    asm volatile("mbarrier.init.shared.b64 [%0], %1;" :: "r"(m), "r"(c) : "memory");
}
__device__ __forceinline__ void mbar_wait(uint32_t m, uint32_t par) {
    asm volatile(
        "{\n\t.reg .pred P;\n"
        "W_%=:\n\t"
        "mbarrier.try_wait.parity.acquire.cta.shared::cta.b64 P, [%0], %1, 0x989680;\n\t"
        "@!P bra.uni W_%=;\n\t}"
        :: "r"(m), "r"(par) : "memory");
}
__device__ __forceinline__ void tc_alloc(uint32_t slot, uint32_t n) {
    asm volatile("tcgen05.alloc.cta_group::1.sync.aligned.shared::cta.b32 [%0], %1;"
                 :: "r"(slot), "r"(n) : "memory");
}
__device__ __forceinline__ void tc_relinq() {
    asm volatile("tcgen05.relinquish_alloc_permit.cta_group::1.sync.aligned;");
}
__device__ __forceinline__ void tc_dealloc(uint32_t t, uint32_t n) {
    asm volatile("tcgen05.dealloc.cta_group::1.sync.aligned.b32 %0, %1;" :: "r"(t), "r"(n));
}
__device__ __forceinline__ void tc_commit(uint32_t m) {
    asm volatile("tcgen05.commit.cta_group::1.mbarrier::arrive::one.shared::cluster.b64 [%0];"
                 :: "r"(m) : "memory");
}
__device__ __forceinline__ void fence_async() {
    asm volatile("fence.proxy.async.shared::cta;" ::: "memory");
}
__device__ __forceinline__ void tc_fence_after() {
    asm volatile("tcgen05.fence::after_thread_sync;" ::: "memory");
}
__device__ __forceinline__ void tc_wait_ld() {
    asm volatile("tcgen05.wait::ld.sync.aligned;" ::: "memory");
}
__device__ __forceinline__ void mma_ss(uint32_t d, uint64_t a, uint64_t b, uint32_t en) {
    asm volatile(
        "{\n\t.reg .pred p;\n\t"
        "setp.ne.u32 p, %5, 0;\n\t"
        "tcgen05.mma.cta_group::1.kind::tf32 [%0], %1, %2, %3, {%4,%4,%4,%4}, p;\n\t}"
        :: "r"(d), "l"(a), "l"(b), "r"(IDESC_TF32), "r"(0u), "r"(en) : "memory");
}
__device__ __forceinline__ uint64_t mk_desc(uint32_t addr) {
    const uint64_t base = (uint64_t(2) << 61) | (uint64_t(1) << 46) |
                          (uint64_t(64) << 32) | (uint64_t(1) << 16);
    return base | ((uint64_t)(addr >> 4) & 0x3FFF);
}
__device__ __forceinline__ void cp16(uint32_t dst, const void* src) {
    asm volatile("cp.async.cg.shared.global [%0], [%1], 16;" :: "r"(dst), "l"(src) : "memory");
}
__device__ __forceinline__ void cp4(uint32_t dst, const void* src) {
    asm volatile("cp.async.ca.shared.global [%0], [%1], 4;" :: "r"(dst), "l"(src) : "memory");
}
__device__ __forceinline__ void cp_commit() {
    asm volatile("cp.async.commit_group;" ::: "memory");
}
template <int N>
__device__ __forceinline__ void cp_wait() {
    asm volatile("cp.async.wait_group %0;" :: "n"(N) : "memory");
}
#define TC_LD32(r, a) \
    asm volatile( \
        "tcgen05.ld.sync.aligned.32x32b.x32.b32 " \
        "{%0,%1,%2,%3,%4,%5,%6,%7,%8,%9,%10,%11,%12,%13,%14,%15," \
        "%16,%17,%18,%19,%20,%21,%22,%23,%24,%25,%26,%27,%28,%29,%30,%31}, [%32];" \
        : "=r"((r)[0]),"=r"((r)[1]),"=r"((r)[2]),"=r"((r)[3]),"=r"((r)[4]),"=r"((r)[5]), \
          "=r"((r)[6]),"=r"((r)[7]),"=r"((r)[8]),"=r"((r)[9]),"=r"((r)[10]),"=r"((r)[11]), \
          "=r"((r)[12]),"=r"((r)[13]),"=r"((r)[14]),"=r"((r)[15]),"=r"((r)[16]),"=r"((r)[17]), \
          "=r"((r)[18]),"=r"((r)[19]),"=r"((r)[20]),"=r"((r)[21]),"=r"((r)[22]),"=r"((r)[23]), \
          "=r"((r)[24]),"=r"((r)[25]),"=r"((r)[26]),"=r"((r)[27]),"=r"((r)[28]),"=r"((r)[29]), \
          "=r"((r)[30]),"=r"((r)[31]) : "r"(a))
#endif  // TC_OK

// ---------------- kernel 0: pre-round x to tf32 RNA ----------------
__global__ void k_xr(const float* __restrict__ x) {
    size_t i = (size_t)blockIdx.x * 256 + threadIdx.x;
    float4 v = ((const float4*)x)[i];
    uint4 o;
    asm("cvt.rna.tf32.f32 %0, %1;" : "=r"(o.x) : "f"(v.x));
    asm("cvt.rna.tf32.f32 %0, %1;" : "=r"(o.y) : "f"(v.y));
    asm("cvt.rna.tf32.f32 %0, %1;" : "=r"(o.z) : "f"(v.z));
    asm("cvt.rna.tf32.f32 %0, %1;" : "=r"(o.w) : "f"(v.w));
    ((uint4*)g_xr)[i] = o;
}

// ---------------- kernel 1: block means ----------------
__global__ void k_bmean(const float* __restrict__ x) {
    int mb = blockIdx.x;
    int c  = blockIdx.y * 512 + threadIdx.x;
    const float* p = x + (size_t)mb * MBM_ * C_DIM + c;
    float s = 0.f;
#pragma unroll
    for (int t = 0; t < MBM_; t++) s += p[(size_t)t * C_DIM];
    g_bmx[mb * C_DIM + c] = s * (1.f / 16.f);
}

// ---------------- kernel 2: selection GEMM (3xTF32) fused bias+|diff|+rsum --------------
__global__ __launch_bounds__(256) void k_sel(const float* __restrict__ fc1w,
                                             const float* __restrict__ fc1b,
                                             const float* __restrict__ bmc) {
    extern __shared__ char dsm[];
    char* base = (char*)((((uintptr_t)dsm) + 1023) & ~(uintptr_t)1023);
    const int tid = threadIdx.x, wid = tid >> 5, lane = tid & 31;

#if TC_OK
    __shared__ uint32_t s_tmem;
    __shared__ uint64_t s_mbar[2];
    const int m0 = blockIdx.x * 128, n0 = blockIdx.y * 128;
    const uint32_t sb = sm32(base);

    if (wid == 0) { tc_alloc(sm32(&s_tmem), 128); tc_relinq(); }
    if (tid == 0) { mbar_init(sm32(&s_mbar[0]), 1); mbar_init(sm32(&s_mbar[1]), 1); }
    __syncthreads();
    const uint32_t tmem = s_tmem;
    const uint32_t mb0 = sm32(&s_mbar[0]), mb1 = sm32(&s_mbar[1]);

    const int row = tid >> 3, c4 = tid & 7;
    float4 ra[4], rb[4];
#pragma unroll
    for (int r = 0; r < 4; r++) {
        int rr = row + 32 * r;
        ra[r] = *(const float4*)(fc1w + (size_t)(m0 + rr) * C_DIM + c4 * 4);
        rb[r] = *(const float4*)(g_bmx + (size_t)(n0 + rr) * C_DIM + c4 * 4);
    }
    const int NCH = C_DIM / 32;  // 96
    for (int i = 0; i < NCH; i++) {
        const int s = i & 1;
        if (i >= 2) mbar_wait(s ? mb1 : mb0, ((i >> 1) - 1) & 1);
        const uint32_t Ah = sb + (s * 4 + 0) * 16384, Al = sb + (s * 4 + 1) * 16384;
        const uint32_t Bh = sb + (s * 4 + 2) * 16384, Bl = sb + (s * 4 + 3) * 16384;
#pragma unroll
        for (int r = 0; r < 4; r++) {
            int rr = row + 32 * r;
            uint32_t off = SWZ(rr * 128 + c4 * 16);
            float av[4] = {ra[r].x, ra[r].y, ra[r].z, ra[r].w};
            float bv[4] = {rb[r].x, rb[r].y, rb[r].z, rb[r].w};
            uint4 h, l;
            h.x = f2tf(av[0]); l.x = f2tf(av[0] - __uint_as_float(h.x));
            h.y = f2tf(av[1]); l.y = f2tf(av[1] - __uint_as_float(h.y));
            h.z = f2tf(av[2]); l.z = f2tf(av[2] - __uint_as_float(h.z));
            h.w = f2tf(av[3]); l.w = f2tf(av[3] - __uint_as_float(h.w));
            *(uint4*)(base + (Ah - sb) + off) = h;
            *(uint4*)(base + (Al - sb) + off) = l;
            h.x = f2tf(bv[0]); l.x = f2tf(bv[0] - __uint_as_float(h.x));
            h.y = f2tf(bv[1]); l.y = f2tf(bv[1] - __uint_as_float(h.y));
            h.z = f2tf(bv[2]); l.z = f2tf(bv[2] - __uint_as_float(h.z));
            h.w = f2tf(bv[3]); l.w = f2tf(bv[3] - __uint_as_float(h.w));
            *(uint4*)(base + (Bh - sb) + off) = h;
            *(uint4*)(base + (Bl - sb) + off) = l;
        }
        fence_async();
        if (i + 1 < NCH) {
            int k0 = (i + 1) * 32;
#pragma unroll
            for (int r = 0; r < 4; r++) {
                int rr = row + 32 * r;
                ra[r] = *(const float4*)(fc1w + (size_t)(m0 + rr) * C_DIM + k0 + c4 * 4);
                rb[r] = *(const float4*)(g_bmx + (size_t)(n0 + rr) * C_DIM + k0 + c4 * 4);
            }
        }
        __syncthreads();
        if (tid == 0) {
            uint64_t dah = mk_desc(Ah), dal = mk_desc(Al);
            uint64_t dbh = mk_desc(Bh), dbl = mk_desc(Bl);
#pragma unroll
            for (int ks = 0; ks < 4; ks++) {
                mma_ss(tmem, dah + ks * 2, dbl + ks * 2, (i | ks) ? 1u : 0u);
                mma_ss(tmem, dal + ks * 2, dbh + ks * 2, 1u);
                mma_ss(tmem, dah + ks * 2, dbh + ks * 2, 1u);
            }
            tc_commit(s ? mb1 : mb0);
        }
    }
    mbar_wait(mb1, 1);
    tc_fence_after();
    const int subp = wid & 3, l = subp * 32 + lane;
    const int f = m0 + l;
    const float bias = fc1b[f];
    const int cb = (wid >> 2) * 64;
    float sum[8];
#pragma unroll
    for (int q = 0; q < 8; q++) sum[q] = 0.f;
#pragma unroll
    for (int g = 0; g < 2; g++) {
        uint32_t d[32];
        TC_LD32(d, tmem + cb + g * 32);
        tc_wait_ld();
#pragma unroll
        for (int j = 0; j < 32; j++) {
            int mbi = n0 + cb + g * 32 + j;
            float val = __uint_as_float(d[j]) + bias;
            sum[(g * 32 + j) >> 3] += fabsf(val - bmc[(size_t)mbi * F_DIM + f]);
        }
    }
    const int b0 = (n0 + cb) >> 3;
#pragma unroll
    for (int q = 0; q < 8; q++) g_mdiff[(size_t)(b0 + q) * F_DIM + f] = sum[q];
    __syncthreads();
    if (wid == 0) tc_dealloc(tmem, 128);

#else
    const int SEL_ST = 20;
    uint32_t* Ah = (uint32_t*)base;
    uint32_t* Al = Ah + 128 * SEL_ST;
    uint32_t* Bh = Al + 128 * SEL_ST;
    uint32_t* Bl = Bh + 128 * SEL_ST;
    float* S = (float*)(Bl + 128 * SEL_ST);
    const int m0 = blockIdx.y * 128, n0 = blockIdx.x * 128;
    const int wm = wid & 1, wn = wid >> 1;
    const int grp = lane >> 2, tig = lane & 3;

    float acc[4][4][4];
#pragma unroll
    for (int i = 0; i < 4; i++)
#pragma unroll
        for (int j = 0; j < 4; j++)
#pragma unroll
            for (int q = 0; q < 4; q++) acc[i][j][q] = 0.f;

    float4 ra[2], rb[2];
    const int lrow = tid >> 2, lc4 = tid & 3;
#pragma unroll
    for (int r = 0; r < 2; r++) {
        int rrow = lrow + 64 * r;
        ra[r] = *(const float4*)(g_bmx + (size_t)(m0 + rrow) * C_DIM + lc4 * 4);
        rb[r] = *(const float4*)(fc1w + (size_t)(n0 + rrow) * C_DIM + lc4 * 4);
    }
    for (int k0 = 0; k0 < C_DIM; k0 += 16) {
#pragma unroll
        for (int r = 0; r < 2; r++) {
            int rrow = lrow + 64 * r;
            int bidx = rrow * SEL_ST + lc4 * 4;
            float av[4] = {ra[r].x, ra[r].y, ra[r].z, ra[r].w};
            float bv[4] = {rb[r].x, rb[r].y, rb[r].z, rb[r].w};
#pragma unroll
            for (int i = 0; i < 4; i++) {
                uint32_t h = f2tf(av[i]);
                Ah[bidx + i] = h;
                Al[bidx + i] = f2tf(av[i] - __uint_as_float(h));
                h = f2tf(bv[i]);
                Bh[bidx + i] = h;
                Bl[bidx + i] = f2tf(bv[i] - __uint_as_float(h));
            }
        }
        __syncthreads();
        if (k0 + 16 < C_DIM) {
#pragma unroll
            for (int r = 0; r < 2; r++) {
                int rrow = lrow + 64 * r;
                ra[r] = *(const float4*)(g_bmx + (size_t)(m0 + rrow) * C_DIM + k0 + 16 + lc4 * 4);
                rb[r] = *(const float4*)(fc1w + (size_t)(n0 + rrow) * C_DIM + k0 + 16 + lc4 * 4);
            }
        }
#pragma unroll
        for (int ks = 0; ks < 2; ks++) {
            const int kk = ks * 8;
            uint32_t ah[4][4], al[4][4], bh[4][2], bl[4][2];
#pragma unroll
            for (int mt = 0; mt < 4; mt++) {
                int mr = wm * 64 + mt * 16 + grp;
                ah[mt][0] = Ah[mr * SEL_ST + kk + tig];
                ah[mt][1] = Ah[(mr + 8) * SEL_ST + kk + tig];
                ah[mt][2] = Ah[mr * SEL_ST + kk + tig + 4];
                ah[mt][3] = Ah[(mr + 8) * SEL_ST + kk + tig + 4];
                al[mt][0] = Al[mr * SEL_ST + kk + tig];
                al[mt][1] = Al[(mr + 8) * SEL_ST + kk + tig];
                al[mt][2] = Al[mr * SEL_ST + kk + tig + 4];
                al[mt][3] = Al[(mr + 8) * SEL_ST + kk + tig + 4];
            }
#pragma unroll
            for (int nt = 0; nt < 4; nt++) {
                int nb = wn * 32 + nt * 8 + grp;
                bh[nt][0] = Bh[nb * SEL_ST + kk + tig];
                bh[nt][1] = Bh[nb * SEL_ST + kk + tig + 4];
                bl[nt][0] = Bl[nb * SEL_ST + kk + tig];
                bl[nt][1] = Bl[nb * SEL_ST + kk + tig + 4];
            }
#pragma unroll
            for (int mt = 0; mt < 4; mt++)
#pragma unroll
                for (int nt = 0; nt < 4; nt++) {
                    mma_frag(acc[mt][nt], ah[mt], bl[nt]);
                    mma_frag(acc[mt][nt], al[mt], bh[nt]);
                    mma_frag(acc[mt][nt], ah[mt], bh[nt]);
                }
        }
        __syncthreads();
    }
#pragma unroll
    for (int mt = 0; mt < 4; mt++)
#pragma unroll
        for (int nt = 0; nt < 4; nt++) {
            int m_l = wm * 64 + mt * 16 + grp;
            int n_l = wn * 32 + nt * 8 + tig * 2;
            S[n_l * 129 + m_l]           = acc[mt][nt][0];
            S[(n_l + 1) * 129 + m_l]     = acc[mt][nt][1];
            S[n_l * 129 + m_l + 8]       = acc[mt][nt][2];
            S[(n_l + 1) * 129 + m_l + 8] = acc[mt][nt][3];
        }
    __syncthreads();
    const int f_l = tid & 127, gh = tid >> 7;
    const int fg = n0 + f_l;
    const float bias = fc1b[fg];
#pragma unroll
    for (int q = 0; q < 8; q++) {
        int mb_l0 = (gh * 8 + q) * 8;
        float s = 0.f;
#pragma unroll
        for (int t = 0; t < 8; t++)
            s += fabsf(S[f_l * 129 + mb_l0 + t] + bias -
                       bmc[(size_t)(m0 + mb_l0 + t) * F_DIM + fg]);
        g_mdiff[(size_t)((m0 + mb_l0) >> 3) * F_DIM + fg] = s;
    }
#endif
}

// ---------------- kernel 3: parallel top-1536 (radix select) ----------------
__global__ __launch_bounds__(1024) void k_topk() {
    const int b = blockIdx.x, tid = threadIdx.x;
    const int lane = tid & 31, w = tid >> 5;
    const float* v = g_mdiff + (size_t)b * F_DIM;
    const int f0 = tid * 12;
    float vals[12];
#pragma unroll
    for (int j = 0; j < 12; j++) vals[j] = v[f0 + j];

    __shared__ int hist[256];
    __shared__ unsigned pref_s;
    __shared__ int rem_s;
    __shared__ int wsum[32];
    __shared__ int total_s;

    unsigned pref = 0;
    int rem = KSEL;
    for (int pass = 0; pass < 4; pass++) {
        const int sh = 24 - 8 * pass;
        if (tid < 256) hist[tid] = 0;
        __syncthreads();
#pragma unroll
        for (int j = 0; j < 12; j++) {
            unsigned u = __float_as_uint(vals[j]);
            if (pass == 0 || (u >> (sh + 8)) == pref)
                atomicAdd(&hist[(u >> sh) & 255], 1);
        }
        __syncthreads();
        for (int off = 1; off < 256; off <<= 1) {
            int x_;
            if (tid < 256) x_ = hist[tid] + ((tid + off < 256) ? hist[tid + off] : 0);
            __syncthreads();
            if (tid < 256) hist[tid] = x_;
            __syncthreads();
        }
        if (tid < 256) {
            int nxt = (tid == 255) ? 0 : hist[tid + 1];
            if (hist[tid] >= rem && nxt < rem) {
                pref_s = (pref << 8) | (unsigned)tid;
                rem_s = rem - nxt;
            }
        }
        __syncthreads();
        pref = pref_s;
        rem = rem_s;
        __syncthreads();
    }
    int cgt = 0, ceq = 0;
#pragma unroll
    for (int j = 0; j < 12; j++) {
        unsigned u = __float_as_uint(vals[j]);
        if (u > pref) cgt++;
        else if (u == pref) ceq++;
    }
    int inc = cgt;
#pragma unroll
    for (int off = 1; off < 32; off <<= 1) {
        int n_ = __shfl_up_sync(0xffffffffu, inc, off);
        if (lane >= off) inc += n_;
    }
    if (lane == 31) wsum[w] = inc;
    __syncthreads();
    if (w == 0) {
        int t = wsum[lane];
#pragma unroll
        for (int off = 1; off < 32; off <<= 1) {
            int n_ = __shfl_up_sync(0xffffffffu, t, off);
            if (lane >= off) t += n_;
        }
        wsum[lane] = t;
    }
    __syncthreads();
    int basep = (w > 0 ? wsum[w - 1] : 0) + inc - cgt;
    if (tid == 1023) total_s = basep + cgt;
    __syncthreads();
    const int total_gt = total_s;
    {
        int pos = basep;
#pragma unroll
        for (int j = 0; j < 12; j++)
            if (__float_as_uint(vals[j]) > pref) g_inds[b * KSEL + (pos++)] = f0 + j;
    }
    __syncthreads();
    inc = ceq;
#pragma unroll
    for (int off = 1; off < 32; off <<= 1) {
        int n_ = __shfl_up_sync(0xffffffffu, inc, off);
        if (lane >= off) inc += n_;
    }
    if (lane == 31) wsum[w] = inc;
    __syncthreads();
    if (w == 0) {
        int t = wsum[lane];
#pragma unroll
        for (int off = 1; off < 32; off <<= 1) {
            int n_ = __shfl_up_sync(0xffffffffu, t, off);
            if (lane >= off) t += n_;
        }
        wsum[lane] = t;
    }
    __syncthreads();
    int ebase = (w > 0 ? wsum[w - 1] : 0) + inc - ceq;
    const int need = KSEL - total_gt;
#pragma unroll
    for (int j = 0; j < 12; j++)
        if (__float_as_uint(vals[j]) == pref) {
            if (ebase < need) g_inds[b * KSEL + total_gt + ebase] = f0 + j;
            ebase++;
        }
}

#if TC_OK
// ---- shared epilogues ----
__device__ __forceinline__ void gemm1_epilogue(uint32_t tmem, const int* ridx,
                                               const float* bsh, const float* sAT,
                                               int blk, int mchunk, int tid) {
    const int wid = tid >> 5, lane = tid & 31;
    const int subp = wid & 3, tok = subp * 32 + lane;
    const int cb = (wid >> 2) * 64;
#pragma unroll
    for (int g = 0; g < 2; g++) {
        uint32_t d[32];
        TC_LD32(d, tmem + cb + g * 32);
        tc_wait_ld();
        uint32_t o[32];
#pragma unroll
        for (int j = 0; j < 32; j++) {
            int chl = cb + g * 32 + j;
            float vm = __uint_as_float(d[j]) + bsh[chl];
            float cached = sAT[(size_t)ridx[chl] * NTOK + blk * BM_ + tok];
            o[j] = f2tf(gelu_t(vm) - cached);
        }
        float* dp = g_delta + ((size_t)blk * BM_ + tok) * KSEL + mchunk * 128 + cb + g * 32;
#pragma unroll
        for (int q = 0; q < 8; q++) *(uint4*)(dp + q * 4) = *(uint4*)&o[q * 4];
    }
}
__device__ __forceinline__ void gemm2_epilogue(uint32_t tmem, const float* out_cache,
                                               float* out, int blk, int n0, int tid) {
    const int wid = tid >> 5, lane = tid & 31;
    const int subp = wid & 3, tok = subp * 32 + lane;
    const int cb = (wid >> 2) * 64;
#pragma unroll
    for (int g = 0; g < 2; g++) {
        uint32_t d[32];
        TC_LD32(d, tmem + cb + g * 32);
        tc_wait_ld();
        size_t off = (size_t)(blk * BM_ + tok) * C_DIM + n0 + cb + g * 32;
#pragma unroll
        for (int q = 0; q < 8; q++) {
            float4 oc = *(const float4*)(out_cache + off + q * 4);
            oc.x += __uint_as_float(d[q * 4 + 0]);
            oc.y += __uint_as_float(d[q * 4 + 1]);
            oc.z += __uint_as_float(d[q * 4 + 2]);
            oc.w += __uint_as_float(d[q * 4 + 3]);
            *(float4*)(out + off + q * 4) = oc;
        }
    }
}
#endif

// ---------------- kernel 4: gemm1 (K16 half-slots, 6 slots, lag-3) ----------------
__global__ __launch_bounds__(256) void k_gemm1(const float* __restrict__ x,
                                               const float* __restrict__ fc1w,
                                               const float* __restrict__ fc1b,
                                               const float* __restrict__ sAT) {
    extern __shared__ char dsm[];
    char* base = (char*)((((uintptr_t)dsm) + 1023) & ~(uintptr_t)1023);
    __shared__ int ridx[128];
    __shared__ float bsh[128];
    const int tid = threadIdx.x, wid = tid >> 5, lane = tid & 31;
    const int blk = blockIdx.y, mchunk = blockIdx.x;

#if TC_OK
    __shared__ uint32_t s_tmem;
    __shared__ uint64_t s_mbar[6];
    const uint32_t sb = sm32(base);

    if (wid == 0) { tc_alloc(sm32(&s_tmem), 128); tc_relinq(); }
    if (tid == 0)
        for (int q = 0; q < 6; q++) mbar_init(sm32(&s_mbar[q]), 1);
    if (tid < 128) {
        int id = g_inds[blk * KSEL + mchunk * 128 + tid];
        ridx[tid] = id;
        bsh[tid] = fc1b[id];
    }
    __syncthreads();
    const uint32_t tmem = s_tmem;
    uint32_t mbx[6];
#pragma unroll
    for (int q = 0; q < 6; q++) mbx[q] = sm32(&s_mbar[q]);

    const float* xb = g_xr + (size_t)blk * BM_ * C_DIM;
    const int row2 = tid >> 1, pp = tid & 1;
    const int NCH = C_DIM / 16;  // 192 half-chunks

    // prologue: chunks 0..2 (slots 0..2)
#pragma unroll
    for (int j = 0; j < 3; j++) {
        const uint32_t At = sb + (j >> 1) * 32768, Bt = At + 16384;
        const int cb64 = (j & 1) * 64, k0 = j * 16;
#pragma unroll
        for (int e = 0; e < 2; e++) {
            int bc = cb64 + pp * 32 + e * 16;
            int kk = pp * 8 + e * 4;
            cp16(At + SWZ(row2 * 128 + bc), xb + (size_t)row2 * C_DIM + k0 + kk);
            cp16(Bt + SWZ(row2 * 128 + bc), fc1w + (size_t)ridx[row2] * C_DIM + k0 + kk);
        }
        cp_commit();
    }
    for (int i = 0; i < NCH; i++) {
        // load chunk i+3 into slot (i+3)%6; previous tenant = chunk i-3
        if (i + 3 < NCH) {
            if (i >= 3) mbar_wait(mbx[(i - 3) % 6], ((i - 3) / 6) & 1);
            const int j = i + 3, sl = j % 6;
            const uint32_t At = sb + (sl >> 1) * 32768, Bt = At + 16384;
            const int cb64 = (sl & 1) * 64, k0 = j * 16;
#pragma unroll
            for (int e = 0; e < 2; e++) {
                int bc = cb64 + pp * 32 + e * 16;
                int kk = pp * 8 + e * 4;
                cp16(At + SWZ(row2 * 128 + bc), xb + (size_t)row2 * C_DIM + k0 + kk);
                cp16(Bt + SWZ(row2 * 128 + bc), fc1w + (size_t)ridx[row2] * C_DIM + k0 + kk);
            }
        }
        cp_commit();
        cp_wait<3>();
        fence_async();
        __syncthreads();
        const int sl = i % 6;
        if (tid == 0) {
            const uint32_t At = sb + (sl >> 1) * 32768, Bt = At + 16384;
            uint64_t da = mk_desc(At) + (sl & 1) * 4;
            uint64_t db = mk_desc(Bt) + (sl & 1) * 4;
            mma_ss(tmem, da, db, i ? 1u : 0u);
            mma_ss(tmem, da + 2, db + 2, 1u);
            tc_commit(mbx[sl]);
        }
    }
    mbar_wait(mbx[(NCH - 1) % 6], ((NCH - 1) / 6) & 1);
    tc_fence_after();
    gemm1_epilogue(tmem, ridx, bsh, sAT, blk, mchunk, tid);
    __syncthreads();
    if (wid == 0) tc_dealloc(tmem, 128);

#else
    // fallback: mma.sync, C[ch][tok], delta stored [blk][ch][tok]
    const int G1_ST = 36;
    uint32_t* As = (uint32_t*)base;
    uint32_t* Bs = As + 128 * G1_ST;
    const int wm = wid & 1, wn = wid >> 1;
    const int grp = lane >> 2, tig = lane & 3;

    if (tid < 128) {
        int id = g_inds[blk * KSEL + mchunk * 128 + tid];
        ridx[tid] = id;
        bsh[tid] = fc1b[id];
    }
    __syncthreads();
    float acc[4][4][4];
#pragma unroll
    for (int i = 0; i < 4; i++)
#pragma unroll
        for (int j = 0; j < 4; j++)
#pragma unroll
            for (int q = 0; q < 4; q++) acc[i][j][q] = 0.f;

    const float* xb = x + (size_t)blk * BM_ * C_DIM;
    const int lrow = tid >> 3, lc4 = tid & 7;
    float4 ra[4], rb[4];
#pragma unroll
    for (int r = 0; r < 4; r++) {
        int rrow = lrow + 32 * r;
        ra[r] = *(const float4*)(fc1w + (size_t)ridx[rrow] * C_DIM + lc4 * 4);
        rb[r] = *(const float4*)(xb + (size_t)rrow * C_DIM + lc4 * 4);
    }
    for (int k0 = 0; k0 < C_DIM; k0 += 32) {
#pragma unroll
        for (int r = 0; r < 4; r++) {
            int rrow = lrow + 32 * r;
            int bidx = rrow * G1_ST + lc4 * 4;
            As[bidx + 0] = f2tf(ra[r].x); As[bidx + 1] = f2tf(ra[r].y);
            As[bidx + 2] = f2tf(ra[r].z); As[bidx + 3] = f2tf(ra[r].w);
            Bs[bidx + 0] = f2tf(rb[r].x); Bs[bidx + 1] = f2tf(rb[r].y);
            Bs[bidx + 2] = f2tf(rb[r].z); Bs[bidx + 3] = f2tf(rb[r].w);
        }
        __syncthreads();
        if (k0 + 32 < C_DIM) {
#pragma unroll
            for (int r = 0; r < 4; r++) {
                int rrow = lrow + 32 * r;
                ra[r] = *(const float4*)(fc1w + (size_t)ridx[rrow] * C_DIM + k0 + 32 + lc4 * 4);
                rb[r] = *(const float4*)(xb + (size_t)rrow * C_DIM + k0 + 32 + lc4 * 4);
            }
        }
#pragma unroll
        for (int ks = 0; ks < 4; ks++) {
            const int kk = ks * 8;
            uint32_t af[4][4], bf[4][2];
#pragma unroll
            for (int mt = 0; mt < 4; mt++) {
                int mr = wm * 64 + mt * 16 + grp;
                af[mt][0] = As[mr * G1_ST + kk + tig];
                af[mt][1] = As[(mr + 8) * G1_ST + kk + tig];
                af[mt][2] = As[mr * G1_ST + kk + tig + 4];
                af[mt][3] = As[(mr + 8) * G1_ST + kk + tig + 4];
            }
#pragma unroll
            for (int nt = 0; nt < 4; nt++) {
                int nb = wn * 32 + nt * 8 + grp;
                bf[nt][0] = Bs[nb * G1_ST + kk + tig];
                bf[nt][1] = Bs[nb * G1_ST + kk + tig + 4];
            }
#pragma unroll
            for (int mt = 0; mt < 4; mt++)
#pragma unroll
                for (int nt = 0; nt < 4; nt++) mma_frag(acc[mt][nt], af[mt], bf[nt]);
        }
        __syncthreads();
    }
#pragma unroll
    for (int mt = 0; mt < 4; mt++)
#pragma unroll
        for (int nt = 0; nt < 4; nt++) {
            int t0 = wn * 32 + nt * 8 + tig * 2;
#pragma unroll
            for (int half = 0; half < 2; half++) {
                int r = wm * 64 + mt * 16 + grp + 8 * half;
                float bb = bsh[r];
                int chg = ridx[r];
                const float* cp = sAT + (size_t)chg * NTOK + blk * BM_ + t0;
                float2 cached = *(const float2*)cp;
                float v0 = acc[mt][nt][half * 2 + 0] + bb;
                float v1 = acc[mt][nt][half * 2 + 1] + bb;
                float2 o;
                o.x = gelu_t(v0) - cached.x;
                o.y = gelu_t(v1) - cached.y;
                *(float2*)(g_delta + ((size_t)blk * KSEL + mchunk * 128 + r) * BM_ + t0) = o;
            }
        }
#endif
}

// ---------------- kernel 5: gemm2 (K16 half-slots, 6 slots, lag-3) ----------------
__global__ __launch_bounds__(256) void k_gemm2(const float* __restrict__ fc2wT,
                                               const float* __restrict__ out_cache,
                                               float* __restrict__ out) {
    extern __shared__ char dsm[];
    char* base = (char*)((((uintptr_t)dsm) + 1023) & ~(uintptr_t)1023);
    __shared__ int kid[KSEL];
    const int tid = threadIdx.x, wid = tid >> 5, lane = tid & 31;
    const int blk = blockIdx.y, n0 = blockIdx.x * 128;

#if TC_OK
    __shared__ uint32_t s_tmem;
    __shared__ uint64_t s_mbar[6];
    const uint32_t sb = sm32(base);

    if (wid == 0) { tc_alloc(sm32(&s_tmem), 128); tc_relinq(); }
    if (tid == 0)
        for (int q = 0; q < 6; q++) mbar_init(sm32(&s_mbar[q]), 1);
    for (int i = tid; i < KSEL; i += 256) kid[i] = g_inds[blk * KSEL + i];
    __syncthreads();
    const uint32_t tmem = s_tmem;
    uint32_t mbx[6];
#pragma unroll
    for (int q = 0; q < 6; q++) mbx[q] = sm32(&s_mbar[q]);

    const float* Ab = g_delta + (size_t)blk * BM_ * KSEL;
    const int row2 = tid >> 1, pp = tid & 1;
    const int cB = tid & 127, hB = tid >> 7;
    const int NCH = KSEL / 16;  // 96 half-chunks

#pragma unroll
    for (int j = 0; j < 3; j++) {
        const uint32_t At = sb + (j >> 1) * 32768, Bt = At + 16384;
        const int cb64 = (j & 1) * 64, k0 = j * 16;
#pragma unroll
        for (int e = 0; e < 2; e++) {
            int bc = cb64 + pp * 32 + e * 16;
            cp16(At + SWZ(row2 * 128 + bc), Ab + (size_t)row2 * KSEL + k0 + pp * 8 + e * 4);
        }
#pragma unroll
        for (int u = 0; u < 2; u++) {
            int q = hB * 2 + u;                       // 16B unit index 0..3
            uint32_t db = Bt + SWZ(cB * 128 + cb64 + q * 16);
#pragma unroll
            for (int e = 0; e < 4; e++)
                cp4(db + e * 4, fc2wT + (size_t)kid[k0 + q * 4 + e] * C_DIM + n0 + cB);
        }
        cp_commit();
    }
    for (int i = 0; i < NCH; i++) {
        if (i + 3 < NCH) {
            if (i >= 3) mbar_wait(mbx[(i - 3) % 6], ((i - 3) / 6) & 1);
            const int j = i + 3, sl = j % 6;
            const uint32_t At = sb + (sl >> 1) * 32768, Bt = At + 16384;
            const int cb64 = (sl & 1) * 64, k0 = j * 16;
#pragma unroll
            for (int e = 0; e < 2; e++) {
                int bc = cb64 + pp * 32 + e * 16;
                cp16(At + SWZ(row2 * 128 + bc), Ab + (size_t)row2 * KSEL + k0 + pp * 8 + e * 4);
            }
#pragma unroll
            for (int u = 0; u < 2; u++) {
                int q = hB * 2 + u;
                uint32_t db = Bt + SWZ(cB * 128 + cb64 + q * 16);
#pragma unroll
                for (int e = 0; e < 4; e++)
                    cp4(db + e * 4, fc2wT + (size_t)kid[k0 + q * 4 + e] * C_DIM + n0 + cB);
            }
        }
        cp_commit();
        cp_wait<3>();
        fence_async();
        __syncthreads();
        const int sl = i % 6;
        if (tid == 0) {
            const uint32_t At = sb + (sl >> 1) * 32768, Bt = At + 16384;
            uint64_t da = mk_desc(At) + (sl & 1) * 4;
            uint64_t db = mk_desc(Bt) + (sl & 1) * 4;
            mma_ss(tmem, da, db, i ? 1u : 0u);
            mma_ss(tmem, da + 2, db + 2, 1u);
            tc_commit(mbx[sl]);
        }
    }
    mbar_wait(mbx[(NCH - 1) % 6], ((NCH - 1) / 6) & 1);
    tc_fence_after();
    gemm2_epilogue(tmem, out_cache, out, blk, n0, tid);
    __syncthreads();
    if (wid == 0) tc_dealloc(tmem, 128);

#else
    const int G2_ST = 136;
    uint32_t* As = (uint32_t*)base;
    uint32_t* Bs = As + 32 * G2_ST;
    const int wm = wid & 1, wn = wid >> 1;
    const int grp = lane >> 2, tig = lane & 3;

    for (int i = tid; i < KSEL; i += 256) kid[i] = g_inds[blk * KSEL + i];
    __syncthreads();

    float acc[4][4][4];
#pragma unroll
    for (int i = 0; i < 4; i++)
#pragma unroll
        for (int j = 0; j < 4; j++)
#pragma unroll
            for (int q = 0; q < 4; q++) acc[i][j][q] = 0.f;

    const float* Ab = g_delta + (size_t)blk * KSEL * BM_;
    float4 ra[4], rb[4];
#pragma unroll
    for (int r = 0; r < 4; r++) {
        int idx = tid + 256 * r;
        int ch = idx >> 5, t4 = idx & 31;
        ra[r] = *(const float4*)(Ab + (size_t)ch * BM_ + t4 * 4);
        rb[r] = *(const float4*)(fc2wT + (size_t)kid[ch] * C_DIM + n0 + t4 * 4);
    }
    for (int k0 = 0; k0 < KSEL; k0 += 32) {
#pragma unroll
        for (int r = 0; r < 4; r++) {
            int idx = tid + 256 * r;
            int ch = idx >> 5, t4 = idx & 31;
            int bidx = ch * G2_ST + t4 * 4;
            As[bidx + 0] = f2tf(ra[r].x); As[bidx + 1] = f2tf(ra[r].y);
            As[bidx + 2] = f2tf(ra[r].z); As[bidx + 3] = f2tf(ra[r].w);
            Bs[bidx + 0] = f2tf(rb[r].x); Bs[bidx + 1] = f2tf(rb[r].y);
            Bs[bidx + 2] = f2tf(rb[r].z); Bs[bidx + 3] = f2tf(rb[r].w);
        }
        __syncthreads();
        if (k0 + 32 < KSEL) {
#pragma unroll
            for (int r = 0; r < 4; r++) {
                int idx = tid + 256 * r;
                int ch = idx >> 5, t4 = idx & 31;
                ra[r] = *(const float4*)(Ab + (size_t)(k0 + 32 + ch) * BM_ + t4 * 4);
                rb[r] = *(const float4*)(fc2wT + (size_t)kid[k0 + 32 + ch] * C_DIM + n0 + t4 * 4);
            }
        }
#pragma unroll
        for (int ks = 0; ks < 4; ks++) {
            const int kk = ks * 8;
            uint32_t af[4][4], bf[4][2];
#pragma unroll
            for (int mt = 0; mt < 4; mt++) {
                int mbr = wm * 64 + mt * 16 + grp;
                af[mt][0] = As[(kk + tig) * G2_ST + mbr];
                af[mt][1] = As[(kk + tig) * G2_ST + mbr + 8];
                af[mt][2] = As[(kk + tig + 4) * G2_ST + mbr];
                af[mt][3] = As[(kk + tig + 4) * G2_ST + mbr + 8];
            }
#pragma unroll
            for (int nt = 0; nt < 4; nt++) {
                int nb = wn * 32 + nt * 8 + grp;
                bf[nt][0] = Bs[(kk + tig) * G2_ST + nb];
                bf[nt][1] = Bs[(kk + tig + 4) * G2_ST + nb];
            }
#pragma unroll
            for (int mt = 0; mt < 4; mt++)
#pragma unroll
                for (int nt = 0; nt < 4; nt++) mma_frag(acc[mt][nt], af[mt], bf[nt]);
        }
        __syncthreads();
    }
#pragma unroll
    for (int mt = 0; mt < 4; mt++)
#pragma unroll
        for (int nt = 0; nt < 4; nt++) {
            int col = n0 + wn * 32 + nt * 8 + tig * 2;
#pragma unroll
            for (int half = 0; half < 2; half++) {
                int trow = wm * 64 + mt * 16 + grp + 8 * half;
                size_t off = (size_t)(blk * BM_ + trow) * C_DIM + col;
                float2 oc = *(const float2*)(out_cache + off);
                float2 o;
                o.x = oc.x + acc[mt][nt][half * 2 + 0];
                o.y = oc.y + acc[mt][nt][half * 2 + 1];
                *(float2*)(out + off) = o;
            }
        }
#endif
}

// ---------------- launch ----------------
extern "C" void kernel_launch(void* const* d_in, const int* in_sizes, int n_in,
                              void* d_out, int out_size) {
    const float* x     = (const float*)d_in[0];
    const float* fc1w  = (const float*)d_in[1];
    const float* fc1b  = (const float*)d_in[2];
    const float* fc2wT = (const float*)d_in[3];
    const float* bmc   = (const float*)d_in[4];
    const float* sAT   = (const float*)d_in[5];
    const float* outc  = (const float*)d_in[6];
    float* out = (float*)d_out;

    cudaFuncSetAttribute(k_sel,   cudaFuncAttributeMaxDynamicSharedMemorySize, SEL_SMEM);
    cudaFuncSetAttribute(k_gemm1, cudaFuncAttributeMaxDynamicSharedMemorySize, G_SMEM);
    cudaFuncSetAttribute(k_gemm2, cudaFuncAttributeMaxDynamicSharedMemorySize, G_SMEM);

    k_xr<<<NTOK * C_DIM / 1024, 256>>>(x);
    k_bmean<<<dim3(256, 6), 512>>>(x);
    k_sel<<<dim3(96, 2), 256, SEL_SMEM>>>(fc1w, fc1b, bmc);
    k_topk<<<32, 1024>>>();
    k_gemm1<<<dim3(12, 32), 256, G_SMEM>>>(x, fc1w, fc1b, sAT);
    k_gemm2<<<dim3(24, 32), 256, G_SMEM>>>(fc2wT, outc, out);
}

// round 15
// speedup vs baseline: 1.2647x; 1.2647x over previous
#include <cuda_runtime.h>
#include <cstdint>

#if defined(__CUDA_ARCH_FEAT_SM103_ALL) || defined(__CUDA_ARCH_FEAT_SM100_ALL) || \
    (defined(__CUDA_ARCH_FAMILY_SPECIFIC__) && (__CUDA_ARCH_FAMILY_SPECIFIC__ >= 1000))
#define TC_OK 1
#else
#define TC_OK 0
#endif

#define NTOK 4096
#define C_DIM 3072
#define F_DIM 12288
#define NB 32
#define BM_ 128
#define MBM_ 16
#define MBS 256
#define KSEL 1536

// idesc: dtype F32(1<<4), atype TF32(2<<7), btype TF32(2<<10), N=128(16<<17), M=128(8<<24)
#define IDESC_TF32 ((1u<<4)|(2u<<7)|(2u<<10)|(16u<<17)|(8u<<24))
#define SWZ(o) ((o) ^ (((o) >> 3) & 0x70))

#define SEL_SMEM (8 * 16384 + 1024)
#define G_SMEM   (6 * 16384 + 1024)    // 3 stages x (A 16KB + B 16KB)

// ---------------- scratch ----------------
__device__ float g_bmx[MBS * C_DIM];
__device__ float g_mdiff[NB * F_DIM];
__device__ int   g_inds[NB * KSEL];
__device__ float g_delta[(size_t)NB * BM_ * KSEL];   // [blk][tok][ch], tf32-RNA rounded
__device__ float g_xr[(size_t)NTOK * C_DIM];         // x pre-rounded to tf32-RNA

// ---------------- common helpers ----------------
__device__ __forceinline__ uint32_t f2tf(float x) {
    uint32_t u; asm("cvt.rna.tf32.f32 %0, %1;" : "=r"(u) : "f"(x)); return u;
}
__device__ __forceinline__ float gelu_t(float v) {
    return 0.5f * v * (1.f + tanhf(0.7978845608028654f * (v + 0.044715f * v * v * v)));
}
__device__ __forceinline__ void mma_frag(float c[4], const uint32_t a[4], const uint32_t b[2]) {
    asm volatile(
        "mma.sync.aligned.m16n8k8.row.col.f32.tf32.tf32.f32 "
        "{%0,%1,%2,%3},{%4,%5,%6,%7},{%8,%9},{%0,%1,%2,%3};"
        : "+f"(c[0]), "+f"(c[1]), "+f"(c[2]), "+f"(c[3])
        : "r"(a[0]), "r"(a[1]), "r"(a[2]), "r"(a[3]), "r"(b[0]), "r"(b[1]));
}

#if TC_OK
__device__ __forceinline__ uint32_t sm32(const void* p) {
    uint32_t a;
    asm("{ .reg .u64 t; cvta.to.shared.u64 t, %1; cvt.u32.u64 %0, t; }" : "=r"(a) : "l"(p));
    return a;
}
__device__ __forceinline__ void mbar_init(uint32_t m, uint32_t c) {
    asm volatile("mbarrier.init.shared.b64 [%0], %1;" :: "r"(m), "r"(c) : "memory");
}
__device__ __forceinline__ void mbar_wait(uint32_t m, uint32_t par) {
    asm volatile(
        "{\n\t.reg .pred P;\n"
        "W_%=:\n\t"
        "mbarrier.try_wait.parity.acquire.cta.shared::cta.b64 P, [%0], %1, 0x989680;\n\t"
        "@!P bra.uni W_%=;\n\t}"
        :: "r"(m), "r"(par) : "memory");
}
__device__ __forceinline__ void tc_alloc(uint32_t slot, uint32_t n) {
    asm volatile("tcgen05.alloc.cta_group::1.sync.aligned.shared::cta.b32 [%0], %1;"
                 :: "r"(slot), "r"(n) : "memory");
}
__device__ __forceinline__ void tc_relinq() {
    asm volatile("tcgen05.relinquish_alloc_permit.cta_group::1.sync.aligned;");
}
__device__ __forceinline__ void tc_dealloc(uint32_t t, uint32_t n) {
    asm volatile("tcgen05.dealloc.cta_group::1.sync.aligned.b32 %0, %1;" :: "r"(t), "r"(n));
}
__device__ __forceinline__ void tc_commit(uint32_t m) {
    asm volatile("tcgen05.commit.cta_group::1.mbarrier::arrive::one.shared::cluster.b64 [%0];"
                 :: "r"(m) : "memory");
}
__device__ __forceinline__ void fence_async() {
    asm volatile("fence.proxy.async.shared::cta;" ::: "memory");
}
__device__ __forceinline__ void tc_fence_after() {
    asm volatile("tcgen05.fence::after_thread_sync;" ::: "memory");
}
__device__ __forceinline__ void tc_wait_ld() {
    asm volatile("tcgen05.wait::ld.sync.aligned;" ::: "memory");
}
__device__ __forceinline__ void mma_ss(uint32_t d, uint64_t a, uint64_t b, uint32_t en) {
    asm volatile(
        "{\n\t.reg .pred p;\n\t"
        "setp.ne.u32 p, %5, 0;\n\t"
        "tcgen05.mma.cta_group::1.kind::tf32 [%0], %1, %2, %3, {%4,%4,%4,%4}, p;\n\t}"
        :: "r"(d), "l"(a), "l"(b), "r"(IDESC_TF32), "r"(0u), "r"(en) : "memory");
}
__device__ __forceinline__ uint64_t mk_desc(uint32_t addr) {
    const uint64_t base = (uint64_t(2) << 61) | (uint64_t(1) << 46) |
                          (uint64_t(64) << 32) | (uint64_t(1) << 16);
    return base | ((uint64_t)(addr >> 4) & 0x3FFF);
}
__device__ __forceinline__ void cp16(uint32_t dst, const void* src) {
    asm volatile("cp.async.cg.shared.global [%0], [%1], 16;" :: "r"(dst), "l"(src) : "memory");
}
__device__ __forceinline__ void cp4(uint32_t dst, const void* src) {
    asm volatile("cp.async.ca.shared.global [%0], [%1], 4;" :: "r"(dst), "l"(src) : "memory");
}
__device__ __forceinline__ void cp_commit() {
    asm volatile("cp.async.commit_group;" ::: "memory");
}
template <int N>
__device__ __forceinline__ void cp_wait() {
    asm volatile("cp.async.wait_group %0;" :: "n"(N) : "memory");
}
#define TC_LD32(r, a) \
    asm volatile( \
        "tcgen05.ld.sync.aligned.32x32b.x32.b32 " \
        "{%0,%1,%2,%3,%4,%5,%6,%7,%8,%9,%10,%11,%12,%13,%14,%15," \
        "%16,%17,%18,%19,%20,%21,%22,%23,%24,%25,%26,%27,%28,%29,%30,%31}, [%32];" \
        : "=r"((r)[0]),"=r"((r)[1]),"=r"((r)[2]),"=r"((r)[3]),"=r"((r)[4]),"=r"((r)[5]), \
          "=r"((r)[6]),"=r"((r)[7]),"=r"((r)[8]),"=r"((r)[9]),"=r"((r)[10]),"=r"((r)[11]), \
          "=r"((r)[12]),"=r"((r)[13]),"=r"((r)[14]),"=r"((r)[15]),"=r"((r)[16]),"=r"((r)[17]), \
          "=r"((r)[18]),"=r"((r)[19]),"=r"((r)[20]),"=r"((r)[21]),"=r"((r)[22]),"=r"((r)[23]), \
          "=r"((r)[24]),"=r"((r)[25]),"=r"((r)[26]),"=r"((r)[27]),"=r"((r)[28]),"=r"((r)[29]), \
          "=r"((r)[30]),"=r"((r)[31]) : "r"(a))
#endif  // TC_OK

// ---------------- kernel 0: pre-round x to tf32 RNA ----------------
__global__ void k_xr(const float* __restrict__ x) {
    size_t i = (size_t)blockIdx.x * 256 + threadIdx.x;
    float4 v = ((const float4*)x)[i];
    uint4 o;
    asm("cvt.rna.tf32.f32 %0, %1;" : "=r"(o.x) : "f"(v.x));
    asm("cvt.rna.tf32.f32 %0, %1;" : "=r"(o.y) : "f"(v.y));
    asm("cvt.rna.tf32.f32 %0, %1;" : "=r"(o.z) : "f"(v.z));
    asm("cvt.rna.tf32.f32 %0, %1;" : "=r"(o.w) : "f"(v.w));
    ((uint4*)g_xr)[i] = o;
}

// ---------------- kernel 1: block means ----------------
__global__ void k_bmean(const float* __restrict__ x) {
    int mb = blockIdx.x;
    int c  = blockIdx.y * 512 + threadIdx.x;
    const float* p = x + (size_t)mb * MBM_ * C_DIM + c;
    float s = 0.f;
#pragma unroll
    for (int t = 0; t < MBM_; t++) s += p[(size_t)t * C_DIM];
    g_bmx[mb * C_DIM + c] = s * (1.f / 16.f);
}

// ---------------- kernel 2: selection GEMM (3xTF32) fused bias+|diff|+rsum --------------
__global__ __launch_bounds__(256) void k_sel(const float* __restrict__ fc1w,
                                             const float* __restrict__ fc1b,
                                             const float* __restrict__ bmc) {
    extern __shared__ char dsm[];
    char* base = (char*)((((uintptr_t)dsm) + 1023) & ~(uintptr_t)1023);
    const int tid = threadIdx.x, wid = tid >> 5, lane = tid & 31;

#if TC_OK
    __shared__ uint32_t s_tmem;
    __shared__ uint64_t s_mbar[2];
    const int m0 = blockIdx.x * 128, n0 = blockIdx.y * 128;
    const uint32_t sb = sm32(base);

    if (wid == 0) { tc_alloc(sm32(&s_tmem), 128); tc_relinq(); }
    if (tid == 0) { mbar_init(sm32(&s_mbar[0]), 1); mbar_init(sm32(&s_mbar[1]), 1); }
    __syncthreads();
    const uint32_t tmem = s_tmem;
    const uint32_t mb0 = sm32(&s_mbar[0]), mb1 = sm32(&s_mbar[1]);

    const int row = tid >> 3, c4 = tid & 7;
    float4 ra[4], rb[4];
#pragma unroll
    for (int r = 0; r < 4; r++) {
        int rr = row + 32 * r;
        ra[r] = *(const float4*)(fc1w + (size_t)(m0 + rr) * C_DIM + c4 * 4);
        rb[r] = *(const float4*)(g_bmx + (size_t)(n0 + rr) * C_DIM + c4 * 4);
    }
    const int NCH = C_DIM / 32;  // 96
    for (int i = 0; i < NCH; i++) {
        const int s = i & 1;
        if (i >= 2) mbar_wait(s ? mb1 : mb0, ((i >> 1) - 1) & 1);
        const uint32_t Ah = sb + (s * 4 + 0) * 16384, Al = sb + (s * 4 + 1) * 16384;
        const uint32_t Bh = sb + (s * 4 + 2) * 16384, Bl = sb + (s * 4 + 3) * 16384;
#pragma unroll
        for (int r = 0; r < 4; r++) {
            int rr = row + 32 * r;
            uint32_t off = SWZ(rr * 128 + c4 * 16);
            float av[4] = {ra[r].x, ra[r].y, ra[r].z, ra[r].w};
            float bv[4] = {rb[r].x, rb[r].y, rb[r].z, rb[r].w};
            uint4 h, l;
            h.x = f2tf(av[0]); l.x = f2tf(av[0] - __uint_as_float(h.x));
            h.y = f2tf(av[1]); l.y = f2tf(av[1] - __uint_as_float(h.y));
            h.z = f2tf(av[2]); l.z = f2tf(av[2] - __uint_as_float(h.z));
            h.w = f2tf(av[3]); l.w = f2tf(av[3] - __uint_as_float(h.w));
            *(uint4*)(base + (Ah - sb) + off) = h;
            *(uint4*)(base + (Al - sb) + off) = l;
            h.x = f2tf(bv[0]); l.x = f2tf(bv[0] - __uint_as_float(h.x));
            h.y = f2tf(bv[1]); l.y = f2tf(bv[1] - __uint_as_float(h.y));
            h.z = f2tf(bv[2]); l.z = f2tf(bv[2] - __uint_as_float(h.z));
            h.w = f2tf(bv[3]); l.w = f2tf(bv[3] - __uint_as_float(h.w));
            *(uint4*)(base + (Bh - sb) + off) = h;
            *(uint4*)(base + (Bl - sb) + off) = l;
        }
        fence_async();
        if (i + 1 < NCH) {
            int k0 = (i + 1) * 32;
#pragma unroll
            for (int r = 0; r < 4; r++) {
                int rr = row + 32 * r;
                ra[r] = *(const float4*)(fc1w + (size_t)(m0 + rr) * C_DIM + k0 + c4 * 4);
                rb[r] = *(const float4*)(g_bmx + (size_t)(n0 + rr) * C_DIM + k0 + c4 * 4);
            }
        }
        __syncthreads();
        if (tid == 0) {
            uint64_t dah = mk_desc(Ah), dal = mk_desc(Al);
            uint64_t dbh = mk_desc(Bh), dbl = mk_desc(Bl);
#pragma unroll
            for (int ks = 0; ks < 4; ks++) {
                mma_ss(tmem, dah + ks * 2, dbl + ks * 2, (i | ks) ? 1u : 0u);
                mma_ss(tmem, dal + ks * 2, dbh + ks * 2, 1u);
                mma_ss(tmem, dah + ks * 2, dbh + ks * 2, 1u);
            }
            tc_commit(s ? mb1 : mb0);
        }
    }
    mbar_wait(mb1, 1);
    tc_fence_after();
    const int subp = wid & 3, l = subp * 32 + lane;
    const int f = m0 + l;
    const float bias = fc1b[f];
    const int cb = (wid >> 2) * 64;
    float sum[8];
#pragma unroll
    for (int q = 0; q < 8; q++) sum[q] = 0.f;
#pragma unroll
    for (int g = 0; g < 2; g++) {
        uint32_t d[32];
        TC_LD32(d, tmem + cb + g * 32);
        tc_wait_ld();
#pragma unroll
        for (int j = 0; j < 32; j++) {
            int mbi = n0 + cb + g * 32 + j;
            float val = __uint_as_float(d[j]) + bias;
            sum[(g * 32 + j) >> 3] += fabsf(val - bmc[(size_t)mbi * F_DIM + f]);
        }
    }
    const int b0 = (n0 + cb) >> 3;
#pragma unroll
    for (int q = 0; q < 8; q++) g_mdiff[(size_t)(b0 + q) * F_DIM + f] = sum[q];
    __syncthreads();
    if (wid == 0) tc_dealloc(tmem, 128);

#else
    const int SEL_ST = 20;
    uint32_t* Ah = (uint32_t*)base;
    uint32_t* Al = Ah + 128 * SEL_ST;
    uint32_t* Bh = Al + 128 * SEL_ST;
    uint32_t* Bl = Bh + 128 * SEL_ST;
    float* S = (float*)(Bl + 128 * SEL_ST);
    const int m0 = blockIdx.y * 128, n0 = blockIdx.x * 128;
    const int wm = wid & 1, wn = wid >> 1;
    const int grp = lane >> 2, tig = lane & 3;

    float acc[4][4][4];
#pragma unroll
    for (int i = 0; i < 4; i++)
#pragma unroll
        for (int j = 0; j < 4; j++)
#pragma unroll
            for (int q = 0; q < 4; q++) acc[i][j][q] = 0.f;

    float4 ra[2], rb[2];
    const int lrow = tid >> 2, lc4 = tid & 3;
#pragma unroll
    for (int r = 0; r < 2; r++) {
        int rrow = lrow + 64 * r;
        ra[r] = *(const float4*)(g_bmx + (size_t)(m0 + rrow) * C_DIM + lc4 * 4);
        rb[r] = *(const float4*)(fc1w + (size_t)(n0 + rrow) * C_DIM + lc4 * 4);
    }
    for (int k0 = 0; k0 < C_DIM; k0 += 16) {
#pragma unroll
        for (int r = 0; r < 2; r++) {
            int rrow = lrow + 64 * r;
            int bidx = rrow * SEL_ST + lc4 * 4;
            float av[4] = {ra[r].x, ra[r].y, ra[r].z, ra[r].w};
            float bv[4] = {rb[r].x, rb[r].y, rb[r].z, rb[r].w};
#pragma unroll
            for (int i = 0; i < 4; i++) {
                uint32_t h = f2tf(av[i]);
                Ah[bidx + i] = h;
                Al[bidx + i] = f2tf(av[i] - __uint_as_float(h));
                h = f2tf(bv[i]);
                Bh[bidx + i] = h;
                Bl[bidx + i] = f2tf(bv[i] - __uint_as_float(h));
            }
        }
        __syncthreads();
        if (k0 + 16 < C_DIM) {
#pragma unroll
            for (int r = 0; r < 2; r++) {
                int rrow = lrow + 64 * r;
                ra[r] = *(const float4*)(g_bmx + (size_t)(m0 + rrow) * C_DIM + k0 + 16 + lc4 * 4);
                rb[r] = *(const float4*)(fc1w + (size_t)(n0 + rrow) * C_DIM + k0 + 16 + lc4 * 4);
            }
        }
#pragma unroll
        for (int ks = 0; ks < 2; ks++) {
            const int kk = ks * 8;
            uint32_t ah[4][4], al[4][4], bh[4][2], bl[4][2];
#pragma unroll
            for (int mt = 0; mt < 4; mt++) {
                int mr = wm * 64 + mt * 16 + grp;
                ah[mt][0] = Ah[mr * SEL_ST + kk + tig];
                ah[mt][1] = Ah[(mr + 8) * SEL_ST + kk + tig];
                ah[mt][2] = Ah[mr * SEL_ST + kk + tig + 4];
                ah[mt][3] = Ah[(mr + 8) * SEL_ST + kk + tig + 4];
                al[mt][0] = Al[mr * SEL_ST + kk + tig];
                al[mt][1] = Al[(mr + 8) * SEL_ST + kk + tig];
                al[mt][2] = Al[mr * SEL_ST + kk + tig + 4];
                al[mt][3] = Al[(mr + 8) * SEL_ST + kk + tig + 4];
            }
#pragma unroll
            for (int nt = 0; nt < 4; nt++) {
                int nb = wn * 32 + nt * 8 + grp;
                bh[nt][0] = Bh[nb * SEL_ST + kk + tig];
                bh[nt][1] = Bh[nb * SEL_ST + kk + tig + 4];
                bl[nt][0] = Bl[nb * SEL_ST + kk + tig];
                bl[nt][1] = Bl[nb * SEL_ST + kk + tig + 4];
            }
#pragma unroll
            for (int mt = 0; mt < 4; mt++)
#pragma unroll
                for (int nt = 0; nt < 4; nt++) {
                    mma_frag(acc[mt][nt], ah[mt], bl[nt]);
                    mma_frag(acc[mt][nt], al[mt], bh[nt]);
                    mma_frag(acc[mt][nt], ah[mt], bh[nt]);
                }
        }
        __syncthreads();
    }
#pragma unroll
    for (int mt = 0; mt < 4; mt++)
#pragma unroll
        for (int nt = 0; nt < 4; nt++) {
            int m_l = wm * 64 + mt * 16 + grp;
            int n_l = wn * 32 + nt * 8 + tig * 2;
            S[n_l * 129 + m_l]           = acc[mt][nt][0];
            S[(n_l + 1) * 129 + m_l]     = acc[mt][nt][1];
            S[n_l * 129 + m_l + 8]       = acc[mt][nt][2];
            S[(n_l + 1) * 129 + m_l + 8] = acc[mt][nt][3];
        }
    __syncthreads();
    const int f_l = tid & 127, gh = tid >> 7;
    const int fg = n0 + f_l;
    const float bias = fc1b[fg];
#pragma unroll
    for (int q = 0; q < 8; q++) {
        int mb_l0 = (gh * 8 + q) * 8;
        float s = 0.f;
#pragma unroll
        for (int t = 0; t < 8; t++)
            s += fabsf(S[f_l * 129 + mb_l0 + t] + bias -
                       bmc[(size_t)(m0 + mb_l0 + t) * F_DIM + fg]);
        g_mdiff[(size_t)((m0 + mb_l0) >> 3) * F_DIM + fg] = s;
    }
#endif
}

// ---------------- kernel 3: parallel top-1536 (radix select) ----------------
__global__ __launch_bounds__(1024) void k_topk() {
    const int b = blockIdx.x, tid = threadIdx.x;
    const int lane = tid & 31, w = tid >> 5;
    const float* v = g_mdiff + (size_t)b * F_DIM;
    const int f0 = tid * 12;
    float vals[12];
#pragma unroll
    for (int j = 0; j < 12; j++) vals[j] = v[f0 + j];

    __shared__ int hist[256];
    __shared__ unsigned pref_s;
    __shared__ int rem_s;
    __shared__ int wsum[32];
    __shared__ int total_s;

    unsigned pref = 0;
    int rem = KSEL;
    for (int pass = 0; pass < 4; pass++) {
        const int sh = 24 - 8 * pass;
        if (tid < 256) hist[tid] = 0;
        __syncthreads();
#pragma unroll
        for (int j = 0; j < 12; j++) {
            unsigned u = __float_as_uint(vals[j]);
            if (pass == 0 || (u >> (sh + 8)) == pref)
                atomicAdd(&hist[(u >> sh) & 255], 1);
        }
        __syncthreads();
        for (int off = 1; off < 256; off <<= 1) {
            int x_;
            if (tid < 256) x_ = hist[tid] + ((tid + off < 256) ? hist[tid + off] : 0);
            __syncthreads();
            if (tid < 256) hist[tid] = x_;
            __syncthreads();
        }
        if (tid < 256) {
            int nxt = (tid == 255) ? 0 : hist[tid + 1];
            if (hist[tid] >= rem && nxt < rem) {
                pref_s = (pref << 8) | (unsigned)tid;
                rem_s = rem - nxt;
            }
        }
        __syncthreads();
        pref = pref_s;
        rem = rem_s;
        __syncthreads();
    }
    int cgt = 0, ceq = 0;
#pragma unroll
    for (int j = 0; j < 12; j++) {
        unsigned u = __float_as_uint(vals[j]);
        if (u > pref) cgt++;
        else if (u == pref) ceq++;
    }
    int inc = cgt;
#pragma unroll
    for (int off = 1; off < 32; off <<= 1) {
        int n_ = __shfl_up_sync(0xffffffffu, inc, off);
        if (lane >= off) inc += n_;
    }
    if (lane == 31) wsum[w] = inc;
    __syncthreads();
    if (w == 0) {
        int t = wsum[lane];
#pragma unroll
        for (int off = 1; off < 32; off <<= 1) {
            int n_ = __shfl_up_sync(0xffffffffu, t, off);
            if (lane >= off) t += n_;
        }
        wsum[lane] = t;
    }
    __syncthreads();
    int basep = (w > 0 ? wsum[w - 1] : 0) + inc - cgt;
    if (tid == 1023) total_s = basep + cgt;
    __syncthreads();
    const int total_gt = total_s;
    {
        int pos = basep;
#pragma unroll
        for (int j = 0; j < 12; j++)
            if (__float_as_uint(vals[j]) > pref) g_inds[b * KSEL + (pos++)] = f0 + j;
    }
    __syncthreads();
    inc = ceq;
#pragma unroll
    for (int off = 1; off < 32; off <<= 1) {
        int n_ = __shfl_up_sync(0xffffffffu, inc, off);
        if (lane >= off) inc += n_;
    }
    if (lane == 31) wsum[w] = inc;
    __syncthreads();
    if (w == 0) {
        int t = wsum[lane];
#pragma unroll
        for (int off = 1; off < 32; off <<= 1) {
            int n_ = __shfl_up_sync(0xffffffffu, t, off);
            if (lane >= off) t += n_;
        }
        wsum[lane] = t;
    }
    __syncthreads();
    int ebase = (w > 0 ? wsum[w - 1] : 0) + inc - ceq;
    const int need = KSEL - total_gt;
#pragma unroll
    for (int j = 0; j < 12; j++)
        if (__float_as_uint(vals[j]) == pref) {
            if (ebase < need) g_inds[b * KSEL + total_gt + ebase] = f0 + j;
            ebase++;
        }
}

#if TC_OK
// ---- shared epilogues ----
__device__ __forceinline__ void gemm1_epilogue(uint32_t tmem, const int* ridx,
                                               const float* bsh, const float* sAT,
                                               int blk, int mchunk, int tid) {
    const int wid = tid >> 5, lane = tid & 31;
    const int subp = wid & 3, tok = subp * 32 + lane;
    const int cb = (wid >> 2) * 64;
#pragma unroll
    for (int g = 0; g < 2; g++) {
        uint32_t d[32];
        TC_LD32(d, tmem + cb + g * 32);
        tc_wait_ld();
        uint32_t o[32];
#pragma unroll
        for (int j = 0; j < 32; j++) {
            int chl = cb + g * 32 + j;
            float vm = __uint_as_float(d[j]) + bsh[chl];
            float cached = sAT[(size_t)ridx[chl] * NTOK + blk * BM_ + tok];
            o[j] = f2tf(gelu_t(vm) - cached);
        }
        float* dp = g_delta + ((size_t)blk * BM_ + tok) * KSEL + mchunk * 128 + cb + g * 32;
#pragma unroll
        for (int q = 0; q < 8; q++) *(uint4*)(dp + q * 4) = *(uint4*)&o[q * 4];
    }
}
__device__ __forceinline__ void gemm2_epilogue(uint32_t tmem, const float* out_cache,
                                               float* out, int blk, int n0, int tid) {
    const int wid = tid >> 5, lane = tid & 31;
    const int subp = wid & 3, tok = subp * 32 + lane;
    const int cb = (wid >> 2) * 64;
#pragma unroll
    for (int g = 0; g < 2; g++) {
        uint32_t d[32];
        TC_LD32(d, tmem + cb + g * 32);
        tc_wait_ld();
        size_t off = (size_t)(blk * BM_ + tok) * C_DIM + n0 + cb + g * 32;
#pragma unroll
        for (int q = 0; q < 8; q++) {
            float4 oc = *(const float4*)(out_cache + off + q * 4);
            oc.x += __uint_as_float(d[q * 4 + 0]);
            oc.y += __uint_as_float(d[q * 4 + 1]);
            oc.z += __uint_as_float(d[q * 4 + 2]);
            oc.w += __uint_as_float(d[q * 4 + 3]);
            *(float4*)(out + off + q * 4) = oc;
        }
    }
}
#endif

// ---------------- kernel 4: gemm1 (R7: 3-stage cp.async) ----------------
__global__ __launch_bounds__(256) void k_gemm1(const float* __restrict__ x,
                                               const float* __restrict__ fc1w,
                                               const float* __restrict__ fc1b,
                                               const float* __restrict__ sAT) {
    extern __shared__ char dsm[];
    char* base = (char*)((((uintptr_t)dsm) + 1023) & ~(uintptr_t)1023);
    __shared__ int ridx[128];
    __shared__ float bsh[128];
    const int tid = threadIdx.x, wid = tid >> 5, lane = tid & 31;
    const int blk = blockIdx.y, mchunk = blockIdx.x;

#if TC_OK
    __shared__ uint32_t s_tmem;
    __shared__ uint64_t s_mbar[3];
    const uint32_t sb = sm32(base);

    if (wid == 0) { tc_alloc(sm32(&s_tmem), 128); tc_relinq(); }
    if (tid == 0)
        for (int q = 0; q < 3; q++) mbar_init(sm32(&s_mbar[q]), 1);
    if (tid < 128) {
        int id = g_inds[blk * KSEL + mchunk * 128 + tid];
        ridx[tid] = id;
        bsh[tid] = fc1b[id];
    }
    __syncthreads();
    const uint32_t tmem = s_tmem;
    uint32_t mbx[3] = {sm32(&s_mbar[0]), sm32(&s_mbar[1]), sm32(&s_mbar[2])};

    const float* xb = g_xr + (size_t)blk * BM_ * C_DIM;
    const int row = tid >> 3, c4 = tid & 7;
    const int NCH = C_DIM / 32;
#pragma unroll
    for (int j = 0; j < 3; j++) {
        const uint32_t At = sb + (j * 2 + 0) * 16384, Bt = sb + (j * 2 + 1) * 16384;
        int k0 = j * 32;
#pragma unroll
        for (int r = 0; r < 4; r++) {
            int rr = row + 32 * r;
            cp16(At + SWZ(rr * 128 + c4 * 16), xb + (size_t)rr * C_DIM + k0 + c4 * 4);
            cp16(Bt + SWZ(rr * 128 + c4 * 16), fc1w + (size_t)ridx[rr] * C_DIM + k0 + c4 * 4);
        }
        cp_commit();
    }
    for (int i = 0; i < NCH; i++) {
        const int b = i % 3;
        if (i < NCH - 2)      cp_wait<2>();
        else if (i == NCH - 2) cp_wait<1>();
        else                   cp_wait<0>();
        fence_async();
        __syncthreads();
        const uint32_t At = sb + (b * 2 + 0) * 16384, Bt = sb + (b * 2 + 1) * 16384;
        if (tid == 0) {
            uint64_t da = mk_desc(At), db = mk_desc(Bt);
#pragma unroll
            for (int ks = 0; ks < 4; ks++)
                mma_ss(tmem, da + ks * 2, db + ks * 2, (i | ks) ? 1u : 0u);
            tc_commit(mbx[b]);
        }
        if (i + 3 < NCH) {
            mbar_wait(mbx[b], (i / 3) & 1);
            int k0 = (i + 3) * 32;
#pragma unroll
            for (int r = 0; r < 4; r++) {
                int rr = row + 32 * r;
                cp16(At + SWZ(rr * 128 + c4 * 16), xb + (size_t)rr * C_DIM + k0 + c4 * 4);
                cp16(Bt + SWZ(rr * 128 + c4 * 16), fc1w + (size_t)ridx[rr] * C_DIM + k0 + c4 * 4);
            }
            cp_commit();
        }
    }
    mbar_wait(mbx[(NCH - 1) % 3], ((NCH - 1) / 3) & 1);
    tc_fence_after();
    gemm1_epilogue(tmem, ridx, bsh, sAT, blk, mchunk, tid);
    __syncthreads();
    if (wid == 0) tc_dealloc(tmem, 128);

#else
    // fallback: mma.sync, C[ch][tok], delta stored [blk][ch][tok]
    const int G1_ST = 36;
    uint32_t* As = (uint32_t*)base;
    uint32_t* Bs = As + 128 * G1_ST;
    const int wm = wid & 1, wn = wid >> 1;
    const int grp = lane >> 2, tig = lane & 3;

    if (tid < 128) {
        int id = g_inds[blk * KSEL + mchunk * 128 + tid];
        ridx[tid] = id;
        bsh[tid] = fc1b[id];
    }
    __syncthreads();
    float acc[4][4][4];
#pragma unroll
    for (int i = 0; i < 4; i++)
#pragma unroll
        for (int j = 0; j < 4; j++)
#pragma unroll
            for (int q = 0; q < 4; q++) acc[i][j][q] = 0.f;

    const float* xb = x + (size_t)blk * BM_ * C_DIM;
    const int lrow = tid >> 3, lc4 = tid & 7;
    float4 ra[4], rb[4];
#pragma unroll
    for (int r = 0; r < 4; r++) {
        int rrow = lrow + 32 * r;
        ra[r] = *(const float4*)(fc1w + (size_t)ridx[rrow] * C_DIM + lc4 * 4);
        rb[r] = *(const float4*)(xb + (size_t)rrow * C_DIM + lc4 * 4);
    }
    for (int k0 = 0; k0 < C_DIM; k0 += 32) {
#pragma unroll
        for (int r = 0; r < 4; r++) {
            int rrow = lrow + 32 * r;
            int bidx = rrow * G1_ST + lc4 * 4;
            As[bidx + 0] = f2tf(ra[r].x); As[bidx + 1] = f2tf(ra[r].y);
            As[bidx + 2] = f2tf(ra[r].z); As[bidx + 3] = f2tf(ra[r].w);
            Bs[bidx + 0] = f2tf(rb[r].x); Bs[bidx + 1] = f2tf(rb[r].y);
            Bs[bidx + 2] = f2tf(rb[r].z); Bs[bidx + 3] = f2tf(rb[r].w);
        }
        __syncthreads();
        if (k0 + 32 < C_DIM) {
#pragma unroll
            for (int r = 0; r < 4; r++) {
                int rrow = lrow + 32 * r;
                ra[r] = *(const float4*)(fc1w + (size_t)ridx[rrow] * C_DIM + k0 + 32 + lc4 * 4);
                rb[r] = *(const float4*)(xb + (size_t)rrow * C_DIM + k0 + 32 + lc4 * 4);
            }
        }
#pragma unroll
        for (int ks = 0; ks < 4; ks++) {
            const int kk = ks * 8;
            uint32_t af[4][4], bf[4][2];
#pragma unroll
            for (int mt = 0; mt < 4; mt++) {
                int mr = wm * 64 + mt * 16 + grp;
                af[mt][0] = As[mr * G1_ST + kk + tig];
                af[mt][1] = As[(mr + 8) * G1_ST + kk + tig];
                af[mt][2] = As[mr * G1_ST + kk + tig + 4];
                af[mt][3] = As[(mr + 8) * G1_ST + kk + tig + 4];
            }
#pragma unroll
            for (int nt = 0; nt < 4; nt++) {
                int nb = wn * 32 + nt * 8 + grp;
                bf[nt][0] = Bs[nb * G1_ST + kk + tig];
                bf[nt][1] = Bs[nb * G1_ST + kk + tig + 4];
            }
#pragma unroll
            for (int mt = 0; mt < 4; mt++)
#pragma unroll
                for (int nt = 0; nt < 4; nt++) mma_frag(acc[mt][nt], af[mt], bf[nt]);
        }
        __syncthreads();
    }
#pragma unroll
    for (int mt = 0; mt < 4; mt++)
#pragma unroll
        for (int nt = 0; nt < 4; nt++) {
            int t0 = wn * 32 + nt * 8 + tig * 2;
#pragma unroll
            for (int half = 0; half < 2; half++) {
                int r = wm * 64 + mt * 16 + grp + 8 * half;
                float bb = bsh[r];
                int chg = ridx[r];
                const float* cp = sAT + (size_t)chg * NTOK + blk * BM_ + t0;
                float2 cached = *(const float2*)cp;
                float v0 = acc[mt][nt][half * 2 + 0] + bb;
                float v1 = acc[mt][nt][half * 2 + 1] + bb;
                float2 o;
                o.x = gelu_t(v0) - cached.x;
                o.y = gelu_t(v1) - cached.y;
                *(float2*)(g_delta + ((size_t)blk * KSEL + mchunk * 128 + r) * BM_ + t0) = o;
            }
        }
#endif
}

// ---------------- kernel 5: gemm2 (R7: 3-stage cp.async, cp4 B transpose) ----------------
__global__ __launch_bounds__(256) void k_gemm2(const float* __restrict__ fc2wT,
                                               const float* __restrict__ out_cache,
                                               float* __restrict__ out) {
    extern __shared__ char dsm[];
    char* base = (char*)((((uintptr_t)dsm) + 1023) & ~(uintptr_t)1023);
    __shared__ int kid[KSEL];
    const int tid = threadIdx.x, wid = tid >> 5, lane = tid & 31;
    const int blk = blockIdx.y, n0 = blockIdx.x * 128;

#if TC_OK
    __shared__ uint32_t s_tmem;
    __shared__ uint64_t s_mbar[3];
    const uint32_t sb = sm32(base);

    if (wid == 0) { tc_alloc(sm32(&s_tmem), 128); tc_relinq(); }
    if (tid == 0)
        for (int q = 0; q < 3; q++) mbar_init(sm32(&s_mbar[q]), 1);
    for (int i = tid; i < KSEL; i += 256) kid[i] = g_inds[blk * KSEL + i];
    __syncthreads();
    const uint32_t tmem = s_tmem;
    uint32_t mbx[3] = {sm32(&s_mbar[0]), sm32(&s_mbar[1]), sm32(&s_mbar[2])};

    const float* Ab = g_delta + (size_t)blk * BM_ * KSEL;
    const int row = tid >> 3, c4 = tid & 7;
    const int cB = tid & 127, ch4b = tid >> 7;
    const int NCH = KSEL / 32;  // 48
#pragma unroll
    for (int j = 0; j < 3; j++) {
        const uint32_t At = sb + (j * 2 + 0) * 16384, Bt = sb + (j * 2 + 1) * 16384;
        int k0 = j * 32;
#pragma unroll
        for (int r = 0; r < 4; r++) {
            int rr = row + 32 * r;
            cp16(At + SWZ(rr * 128 + c4 * 16), Ab + (size_t)rr * KSEL + k0 + c4 * 4);
        }
#pragma unroll
        for (int jj = 0; jj < 4; jj++) {
            int ch4 = ch4b + jj * 2;
            uint32_t db = Bt + SWZ(cB * 128 + ch4 * 16);
#pragma unroll
            for (int q = 0; q < 4; q++)
                cp4(db + q * 4, fc2wT + (size_t)kid[k0 + ch4 * 4 + q] * C_DIM + n0 + cB);
        }
        cp_commit();
    }
    for (int i = 0; i < NCH; i++) {
        const int b = i % 3;
        if (i < NCH - 2)      cp_wait<2>();
        else if (i == NCH - 2) cp_wait<1>();
        else                   cp_wait<0>();
        fence_async();
        __syncthreads();
        const uint32_t At = sb + (b * 2 + 0) * 16384, Bt = sb + (b * 2 + 1) * 16384;
        if (tid == 0) {
            uint64_t da = mk_desc(At), db = mk_desc(Bt);
#pragma unroll
            for (int ks = 0; ks < 4; ks++)
                mma_ss(tmem, da + ks * 2, db + ks * 2, (i | ks) ? 1u : 0u);
            tc_commit(mbx[b]);
        }
        if (i + 3 < NCH) {
            mbar_wait(mbx[b], (i / 3) & 1);
            int k0 = (i + 3) * 32;
#pragma unroll
            for (int r = 0; r < 4; r++) {
                int rr = row + 32 * r;
                cp16(At + SWZ(rr * 128 + c4 * 16), Ab + (size_t)rr * KSEL + k0 + c4 * 4);
            }
#pragma unroll
            for (int jj = 0; jj < 4; jj++) {
                int ch4 = ch4b + jj * 2;
                uint32_t db = Bt + SWZ(cB * 128 + ch4 * 16);
#pragma unroll
                for (int q = 0; q < 4; q++)
                    cp4(db + q * 4, fc2wT + (size_t)kid[k0 + ch4 * 4 + q] * C_DIM + n0 + cB);
            }
            cp_commit();
        }
    }
    mbar_wait(mbx[(NCH - 1) % 3], ((NCH - 1) / 3) & 1);
    tc_fence_after();
    gemm2_epilogue(tmem, out_cache, out, blk, n0, tid);
    __syncthreads();
    if (wid == 0) tc_dealloc(tmem, 128);

#else
    const int G2_ST = 136;
    uint32_t* As = (uint32_t*)base;
    uint32_t* Bs = As + 32 * G2_ST;
    const int wm = wid & 1, wn = wid >> 1;
    const int grp = lane >> 2, tig = lane & 3;

    for (int i = tid; i < KSEL; i += 256) kid[i] = g_inds[blk * KSEL + i];
    __syncthreads();

    float acc[4][4][4];
#pragma unroll
    for (int i = 0; i < 4; i++)
#pragma unroll
        for (int j = 0; j < 4; j++)
#pragma unroll
            for (int q = 0; q < 4; q++) acc[i][j][q] = 0.f;

    const float* Ab = g_delta + (size_t)blk * KSEL * BM_;
    float4 ra[4], rb[4];
#pragma unroll
    for (int r = 0; r < 4; r++) {
        int idx = tid + 256 * r;
        int ch = idx >> 5, t4 = idx & 31;
        ra[r] = *(const float4*)(Ab + (size_t)ch * BM_ + t4 * 4);
        rb[r] = *(const float4*)(fc2wT + (size_t)kid[ch] * C_DIM + n0 + t4 * 4);
    }
    for (int k0 = 0; k0 < KSEL; k0 += 32) {
#pragma unroll
        for (int r = 0; r < 4; r++) {
            int idx = tid + 256 * r;
            int ch = idx >> 5, t4 = idx & 31;
            int bidx = ch * G2_ST + t4 * 4;
            As[bidx + 0] = f2tf(ra[r].x); As[bidx + 1] = f2tf(ra[r].y);
            As[bidx + 2] = f2tf(ra[r].z); As[bidx + 3] = f2tf(ra[r].w);
            Bs[bidx + 0] = f2tf(rb[r].x); Bs[bidx + 1] = f2tf(rb[r].y);
            Bs[bidx + 2] = f2tf(rb[r].z); Bs[bidx + 3] = f2tf(rb[r].w);
        }
        __syncthreads();
        if (k0 + 32 < KSEL) {
#pragma unroll
            for (int r = 0; r < 4; r++) {
                int idx = tid + 256 * r;
                int ch = idx >> 5, t4 = idx & 31;
                ra[r] = *(const float4*)(Ab + (size_t)(k0 + 32 + ch) * BM_ + t4 * 4);
                rb[r] = *(const float4*)(fc2wT + (size_t)kid[k0 + 32 + ch] * C_DIM + n0 + t4 * 4);
            }
        }
#pragma unroll
        for (int ks = 0; ks < 4; ks++) {
            const int kk = ks * 8;
            uint32_t af[4][4], bf[4][2];
#pragma unroll
            for (int mt = 0; mt < 4; mt++) {
                int mbr = wm * 64 + mt * 16 + grp;
                af[mt][0] = As[(kk + tig) * G2_ST + mbr];
                af[mt][1] = As[(kk + tig) * G2_ST + mbr + 8];
                af[mt][2] = As[(kk + tig + 4) * G2_ST + mbr];
                af[mt][3] = As[(kk + tig + 4) * G2_ST + mbr + 8];
            }
#pragma unroll
            for (int nt = 0; nt < 4; nt++) {
                int nb = wn * 32 + nt * 8 + grp;
                bf[nt][0] = Bs[(kk + tig) * G2_ST + nb];
                bf[nt][1] = Bs[(kk + tig + 4) * G2_ST + nb];
            }
#pragma unroll
            for (int mt = 0; mt < 4; mt++)
#pragma unroll
                for (int nt = 0; nt < 4; nt++) mma_frag(acc[mt][nt], af[mt], bf[nt]);
        }
        __syncthreads();
    }
#pragma unroll
    for (int mt = 0; mt < 4; mt++)
#pragma unroll
        for (int nt = 0; nt < 4; nt++) {
            int col = n0 + wn * 32 + nt * 8 + tig * 2;
#pragma unroll
            for (int half = 0; half < 2; half++) {
                int trow = wm * 64 + mt * 16 + grp + 8 * half;
                size_t off = (size_t)(blk * BM_ + trow) * C_DIM + col;
                float2 oc = *(const float2*)(out_cache + off);
                float2 o;
                o.x = oc.x + acc[mt][nt][half * 2 + 0];
                o.y = oc.y + acc[mt][nt][half * 2 + 1];
                *(float2*)(out + off) = o;
            }
        }
#endif
}

// ---------------- launch: fork k_xr onto a side stream, overlap with selection chain ----
extern "C" void kernel_launch(void* const* d_in, const int* in_sizes, int n_in,
                              void* d_out, int out_size) {
    const float* x     = (const float*)d_in[0];
    const float* fc1w  = (const float*)d_in[1];
    const float* fc1b  = (const float*)d_in[2];
    const float* fc2wT = (const float*)d_in[3];
    const float* bmc   = (const float*)d_in[4];
    const float* sAT   = (const float*)d_in[5];
    const float* outc  = (const float*)d_in[6];
    float* out = (float*)d_out;

    cudaFuncSetAttribute(k_sel,   cudaFuncAttributeMaxDynamicSharedMemorySize, SEL_SMEM);
    cudaFuncSetAttribute(k_gemm1, cudaFuncAttributeMaxDynamicSharedMemorySize, G_SMEM);
    cudaFuncSetAttribute(k_gemm2, cudaFuncAttributeMaxDynamicSharedMemorySize, G_SMEM);

    cudaStream_t s1;
    cudaEvent_t e0, e1;
    bool forked = (cudaStreamCreateWithFlags(&s1, cudaStreamNonBlocking) == cudaSuccess) &&
                  (cudaEventCreateWithFlags(&e0, cudaEventDisableTiming) == cudaSuccess) &&
                  (cudaEventCreateWithFlags(&e1, cudaEventDisableTiming) == cudaSuccess);

    if (forked) {
        // fork: side stream runs k_xr concurrently with bmean -> sel -> topk
        cudaEventRecord(e0, 0);
        cudaStreamWaitEvent(s1, e0, 0);
        k_xr<<<NTOK * C_DIM / 1024, 256, 0, s1>>>(x);
        cudaEventRecord(e1, s1);

        k_bmean<<<dim3(256, 6), 512>>>(x);
        k_sel<<<dim3(96, 2), 256, SEL_SMEM>>>(fc1w, fc1b, bmc);
        k_topk<<<32, 1024>>>();

        // join: gemm1 needs both topk (in-stream) and k_xr (side stream)
        cudaStreamWaitEvent(0, e1, 0);
        k_gemm1<<<dim3(12, 32), 256, G_SMEM>>>(x, fc1w, fc1b, sAT);
        k_gemm2<<<dim3(24, 32), 256, G_SMEM>>>(fc2wT, outc, out);

        cudaEventDestroy(e0);
        cudaEventDestroy(e1);
        cudaStreamDestroy(s1);
    } else {
        // serial fallback (exact R7 behavior)
        k_xr<<<NTOK * C_DIM / 1024, 256>>>(x);
        k_bmean<<<dim3(256, 6), 512>>>(x);
        k_sel<<<dim3(96, 2), 256, SEL_SMEM>>>(fc1w, fc1b, bmc);
        k_topk<<<32, 1024>>>();
        k_gemm1<<<dim3(12, 32), 256, G_SMEM>>>(x, fc1w, fc1b, sAT);
        k_gemm2<<<dim3(24, 32), 256, G_SMEM>>>(fc2wT, outc, out);
    }
}

// round 16
// speedup vs baseline: 1.3251x; 1.0477x over previous
#include <cuda_runtime.h>
#include <cstdint>

#if defined(__CUDA_ARCH_FEAT_SM103_ALL) || defined(__CUDA_ARCH_FEAT_SM100_ALL) || \
    (defined(__CUDA_ARCH_FAMILY_SPECIFIC__) && (__CUDA_ARCH_FAMILY_SPECIFIC__ >= 1000))
#define TC_OK 1
#else
#define TC_OK 0
#endif

#define NTOK 4096
#define C_DIM 3072
#define F_DIM 12288
#define NB 32
#define BM_ 128
#define MBM_ 16
#define MBS 256
#define KSEL 1536

// idesc: dtype F32(1<<4), atype TF32(2<<7), btype TF32(2<<10), N=128(16<<17), M=128(8<<24)
#define IDESC_TF32 ((1u<<4)|(2u<<7)|(2u<<10)|(16u<<17)|(8u<<24))
#define SWZ(o) ((o) ^ (((o) >> 3) & 0x70))

#define SEL_SMEM (4 * 16384 + 1024)   // single stage: Ah Al Bh Bl (3 CTAs/SM)
#define G_SMEM   (6 * 16384 + 1024)   // 3 stages x (A 16KB + B 16KB)

// ---------------- scratch ----------------
__device__ float g_bmx[MBS * C_DIM];
__device__ float g_mdiff[NB * F_DIM];
__device__ int   g_inds[NB * KSEL];
__device__ float g_delta[(size_t)NB * BM_ * KSEL];   // [blk][tok][ch], tf32-RNA rounded
__device__ float g_xr[(size_t)NTOK * C_DIM];         // x pre-rounded to tf32-RNA

// ---------------- common helpers ----------------
__device__ __forceinline__ uint32_t f2tf(float x) {
    uint32_t u; asm("cvt.rna.tf32.f32 %0, %1;" : "=r"(u) : "f"(x)); return u;
}
__device__ __forceinline__ float gelu_t(float v) {
    return 0.5f * v * (1.f + tanhf(0.7978845608028654f * (v + 0.044715f * v * v * v)));
}
__device__ __forceinline__ void mma_frag(float c[4], const uint32_t a[4], const uint32_t b[2]) {
    asm volatile(
        "mma.sync.aligned.m16n8k8.row.col.f32.tf32.tf32.f32 "
        "{%0,%1,%2,%3},{%4,%5,%6,%7},{%8,%9},{%0,%1,%2,%3};"
        : "+f"(c[0]), "+f"(c[1]), "+f"(c[2]), "+f"(c[3])
        : "r"(a[0]), "r"(a[1]), "r"(a[2]), "r"(a[3]), "r"(b[0]), "r"(b[1]));
}

#if TC_OK
__device__ __forceinline__ uint32_t sm32(const void* p) {
    uint32_t a;
    asm("{ .reg .u64 t; cvta.to.shared.u64 t, %1; cvt.u32.u64 %0, t; }" : "=r"(a) : "l"(p));
    return a;
}
__device__ __forceinline__ void mbar_init(uint32_t m, uint32_t c) {
    asm volatile("mbarrier.init.shared.b64 [%0], %1;" :: "r"(m), "r"(c) : "memory");
}
__device__ __forceinline__ void mbar_wait(uint32_t m, uint32_t par) {
    asm volatile(
        "{\n\t.reg .pred P;\n"
        "W_%=:\n\t"
        "mbarrier.try_wait.parity.acquire.cta.shared::cta.b64 P, [%0], %1, 0x989680;\n\t"
        "@!P bra.uni W_%=;\n\t}"
        :: "r"(m), "r"(par) : "memory");
}
__device__ __forceinline__ void tc_alloc(uint32_t slot, uint32_t n) {
    asm volatile("tcgen05.alloc.cta_group::1.sync.aligned.shared::cta.b32 [%0], %1;"
                 :: "r"(slot), "r"(n) : "memory");
}
__device__ __forceinline__ void tc_relinq() {
    asm volatile("tcgen05.relinquish_alloc_permit.cta_group::1.sync.aligned;");
}
__device__ __forceinline__ void tc_dealloc(uint32_t t, uint32_t n) {
    asm volatile("tcgen05.dealloc.cta_group::1.sync.aligned.b32 %0, %1;" :: "r"(t), "r"(n));
}
__device__ __forceinline__ void tc_commit(uint32_t m) {
    asm volatile("tcgen05.commit.cta_group::1.mbarrier::arrive::one.shared::cluster.b64 [%0];"
                 :: "r"(m) : "memory");
}
__device__ __forceinline__ void fence_async() {
    asm volatile("fence.proxy.async.shared::cta;" ::: "memory");
}
__device__ __forceinline__ void tc_fence_after() {
    asm volatile("tcgen05.fence::after_thread_sync;" ::: "memory");
}
__device__ __forceinline__ void tc_wait_ld() {
    asm volatile("tcgen05.wait::ld.sync.aligned;" ::: "memory");
}
__device__ __forceinline__ void mma_ss(uint32_t d, uint64_t a, uint64_t b, uint32_t en) {
    asm volatile(
        "{\n\t.reg .pred p;\n\t"
        "setp.ne.u32 p, %5, 0;\n\t"
        "tcgen05.mma.cta_group::1.kind::tf32 [%0], %1, %2, %3, {%4,%4,%4,%4}, p;\n\t}"
        :: "r"(d), "l"(a), "l"(b), "r"(IDESC_TF32), "r"(0u), "r"(en) : "memory");
}
__device__ __forceinline__ uint64_t mk_desc(uint32_t addr) {
    const uint64_t base = (uint64_t(2) << 61) | (uint64_t(1) << 46) |
                          (uint64_t(64) << 32) | (uint64_t(1) << 16);
    return base | ((uint64_t)(addr >> 4) & 0x3FFF);
}
__device__ __forceinline__ void cp16(uint32_t dst, const void* src) {
    asm volatile("cp.async.cg.shared.global [%0], [%1], 16;" :: "r"(dst), "l"(src) : "memory");
}
__device__ __forceinline__ void cp4(uint32_t dst, const void* src) {
    asm volatile("cp.async.ca.shared.global [%0], [%1], 4;" :: "r"(dst), "l"(src) : "memory");
}
__device__ __forceinline__ void cp_commit() {
    asm volatile("cp.async.commit_group;" ::: "memory");
}
template <int N>
__device__ __forceinline__ void cp_wait() {
    asm volatile("cp.async.wait_group %0;" :: "n"(N) : "memory");
}
#define TC_LD32(r, a) \
    asm volatile( \
        "tcgen05.ld.sync.aligned.32x32b.x32.b32 " \
        "{%0,%1,%2,%3,%4,%5,%6,%7,%8,%9,%10,%11,%12,%13,%14,%15," \
        "%16,%17,%18,%19,%20,%21,%22,%23,%24,%25,%26,%27,%28,%29,%30,%31}, [%32];" \
        : "=r"((r)[0]),"=r"((r)[1]),"=r"((r)[2]),"=r"((r)[3]),"=r"((r)[4]),"=r"((r)[5]), \
          "=r"((r)[6]),"=r"((r)[7]),"=r"((r)[8]),"=r"((r)[9]),"=r"((r)[10]),"=r"((r)[11]), \
          "=r"((r)[12]),"=r"((r)[13]),"=r"((r)[14]),"=r"((r)[15]),"=r"((r)[16]),"=r"((r)[17]), \
          "=r"((r)[18]),"=r"((r)[19]),"=r"((r)[20]),"=r"((r)[21]),"=r"((r)[22]),"=r"((r)[23]), \
          "=r"((r)[24]),"=r"((r)[25]),"=r"((r)[26]),"=r"((r)[27]),"=r"((r)[28]),"=r"((r)[29]), \
          "=r"((r)[30]),"=r"((r)[31]) : "r"(a))
#endif  // TC_OK

// ---------------- kernel 0: pre-round x to tf32 RNA ----------------
__global__ void k_xr(const float* __restrict__ x) {
    size_t i = (size_t)blockIdx.x * 256 + threadIdx.x;
    float4 v = ((const float4*)x)[i];
    uint4 o;
    asm("cvt.rna.tf32.f32 %0, %1;" : "=r"(o.x) : "f"(v.x));
    asm("cvt.rna.tf32.f32 %0, %1;" : "=r"(o.y) : "f"(v.y));
    asm("cvt.rna.tf32.f32 %0, %1;" : "=r"(o.z) : "f"(v.z));
    asm("cvt.rna.tf32.f32 %0, %1;" : "=r"(o.w) : "f"(v.w));
    ((uint4*)g_xr)[i] = o;
}

// ---------------- kernel 1: block means ----------------
__global__ void k_bmean(const float* __restrict__ x) {
    int mb = blockIdx.x;
    int c  = blockIdx.y * 512 + threadIdx.x;
    const float* p = x + (size_t)mb * MBM_ * C_DIM + c;
    float s = 0.f;
#pragma unroll
    for (int t = 0; t < MBM_; t++) s += p[(size_t)t * C_DIM];
    g_bmx[mb * C_DIM + c] = s * (1.f / 16.f);
}

// ---------------- kernel 2: selection GEMM (3xTF32), single-stage (3 CTAs/SM) -----------
__global__ __launch_bounds__(256, 3) void k_sel(const float* __restrict__ fc1w,
                                                const float* __restrict__ fc1b,
                                                const float* __restrict__ bmc) {
    extern __shared__ char dsm[];
    char* base = (char*)((((uintptr_t)dsm) + 1023) & ~(uintptr_t)1023);
    const int tid = threadIdx.x, wid = tid >> 5, lane = tid & 31;

#if TC_OK
    __shared__ uint32_t s_tmem;
    __shared__ uint64_t s_mbar;
    const int m0 = blockIdx.x * 128, n0 = blockIdx.y * 128;
    const uint32_t sb = sm32(base);

    if (wid == 0) { tc_alloc(sm32(&s_tmem), 128); tc_relinq(); }
    if (tid == 0) mbar_init(sm32(&s_mbar), 1);
    __syncthreads();
    const uint32_t tmem = s_tmem;
    const uint32_t mb0 = sm32(&s_mbar);

    const uint32_t Ah = sb, Al = sb + 16384, Bh = sb + 32768, Bl = sb + 49152;

    const int row = tid >> 3, c4 = tid & 7;
    float4 ra[4], rb[4];
#pragma unroll
    for (int r = 0; r < 4; r++) {
        int rr = row + 32 * r;
        ra[r] = *(const float4*)(fc1w + (size_t)(m0 + rr) * C_DIM + c4 * 4);
        rb[r] = *(const float4*)(g_bmx + (size_t)(n0 + rr) * C_DIM + c4 * 4);
    }
    const int NCH = C_DIM / 32;  // 96
    for (int i = 0; i < NCH; i++) {
        // single buffer: previous chunk's mma must finish before overwrite
        if (i >= 1) mbar_wait(mb0, (i - 1) & 1);
#pragma unroll
        for (int r = 0; r < 4; r++) {
            int rr = row + 32 * r;
            uint32_t off = SWZ(rr * 128 + c4 * 16);
            float av[4] = {ra[r].x, ra[r].y, ra[r].z, ra[r].w};
            float bv[4] = {rb[r].x, rb[r].y, rb[r].z, rb[r].w};
            uint4 h, l;
            h.x = f2tf(av[0]); l.x = f2tf(av[0] - __uint_as_float(h.x));
            h.y = f2tf(av[1]); l.y = f2tf(av[1] - __uint_as_float(h.y));
            h.z = f2tf(av[2]); l.z = f2tf(av[2] - __uint_as_float(h.z));
            h.w = f2tf(av[3]); l.w = f2tf(av[3] - __uint_as_float(h.w));
            *(uint4*)(base + (Ah - sb) + off) = h;
            *(uint4*)(base + (Al - sb) + off) = l;
            h.x = f2tf(bv[0]); l.x = f2tf(bv[0] - __uint_as_float(h.x));
            h.y = f2tf(bv[1]); l.y = f2tf(bv[1] - __uint_as_float(h.y));
            h.z = f2tf(bv[2]); l.z = f2tf(bv[2] - __uint_as_float(h.z));
            h.w = f2tf(bv[3]); l.w = f2tf(bv[3] - __uint_as_float(h.w));
            *(uint4*)(base + (Bh - sb) + off) = h;
            *(uint4*)(base + (Bl - sb) + off) = l;
        }
        fence_async();
        if (i + 1 < NCH) {
            int k0 = (i + 1) * 32;
#pragma unroll
            for (int r = 0; r < 4; r++) {
                int rr = row + 32 * r;
                ra[r] = *(const float4*)(fc1w + (size_t)(m0 + rr) * C_DIM + k0 + c4 * 4);
                rb[r] = *(const float4*)(g_bmx + (size_t)(n0 + rr) * C_DIM + k0 + c4 * 4);
            }
        }
        __syncthreads();
        if (tid == 0) {
            uint64_t dah = mk_desc(Ah), dal = mk_desc(Al);
            uint64_t dbh = mk_desc(Bh), dbl = mk_desc(Bl);
#pragma unroll
            for (int ks = 0; ks < 4; ks++) {
                mma_ss(tmem, dah + ks * 2, dbl + ks * 2, (i | ks) ? 1u : 0u);
                mma_ss(tmem, dal + ks * 2, dbh + ks * 2, 1u);
                mma_ss(tmem, dah + ks * 2, dbh + ks * 2, 1u);
            }
            tc_commit(mb0);
        }
    }
    mbar_wait(mb0, (NCH - 1) & 1);   // chunk 95 done: parity 1
    tc_fence_after();
    const int subp = wid & 3, l = subp * 32 + lane;
    const int f = m0 + l;
    const float bias = fc1b[f];
    const int cb = (wid >> 2) * 64;
    float sum[8];
#pragma unroll
    for (int q = 0; q < 8; q++) sum[q] = 0.f;
#pragma unroll
    for (int g = 0; g < 2; g++) {
        uint32_t d[32];
        TC_LD32(d, tmem + cb + g * 32);
        tc_wait_ld();
#pragma unroll
        for (int j = 0; j < 32; j++) {
            int mbi = n0 + cb + g * 32 + j;
            float val = __uint_as_float(d[j]) + bias;
            sum[(g * 32 + j) >> 3] += fabsf(val - bmc[(size_t)mbi * F_DIM + f]);
        }
    }
    const int b0 = (n0 + cb) >> 3;
#pragma unroll
    for (int q = 0; q < 8; q++) g_mdiff[(size_t)(b0 + q) * F_DIM + f] = sum[q];
    __syncthreads();
    if (wid == 0) tc_dealloc(tmem, 128);

#else
    // fallback: mma.sync 3xTF32, C[mb][f], fused mdiff epilogue
    // NOTE: requires more smem than SEL_SMEM provides; dead on GB300 (TC path used).
    const int SEL_ST = 20;
    uint32_t* Ah = (uint32_t*)base;
    uint32_t* Al = Ah + 128 * SEL_ST;
    uint32_t* Bh = Al + 128 * SEL_ST;
    uint32_t* Bl = Bh + 128 * SEL_ST;
    float* S = (float*)(Bl + 128 * SEL_ST);
    const int m0 = blockIdx.y * 128, n0 = blockIdx.x * 128;
    const int wm = wid & 1, wn = wid >> 1;
    const int grp = lane >> 2, tig = lane & 3;

    float acc[4][4][4];
#pragma unroll
    for (int i = 0; i < 4; i++)
#pragma unroll
        for (int j = 0; j < 4; j++)
#pragma unroll
            for (int q = 0; q < 4; q++) acc[i][j][q] = 0.f;

    float4 ra[2], rb[2];
    const int lrow = tid >> 2, lc4 = tid & 3;
#pragma unroll
    for (int r = 0; r < 2; r++) {
        int rrow = lrow + 64 * r;
        ra[r] = *(const float4*)(g_bmx + (size_t)(m0 + rrow) * C_DIM + lc4 * 4);
        rb[r] = *(const float4*)(fc1w + (size_t)(n0 + rrow) * C_DIM + lc4 * 4);
    }
    for (int k0 = 0; k0 < C_DIM; k0 += 16) {
#pragma unroll
        for (int r = 0; r < 2; r++) {
            int rrow = lrow + 64 * r;
            int bidx = rrow * SEL_ST + lc4 * 4;
            float av[4] = {ra[r].x, ra[r].y, ra[r].z, ra[r].w};
            float bv[4] = {rb[r].x, rb[r].y, rb[r].z, rb[r].w};
#pragma unroll
            for (int i = 0; i < 4; i++) {
                uint32_t h = f2tf(av[i]);
                Ah[bidx + i] = h;
                Al[bidx + i] = f2tf(av[i] - __uint_as_float(h));
                h = f2tf(bv[i]);
                Bh[bidx + i] = h;
                Bl[bidx + i] = f2tf(bv[i] - __uint_as_float(h));
            }
        }
        __syncthreads();
        if (k0 + 16 < C_DIM) {
#pragma unroll
            for (int r = 0; r < 2; r++) {
                int rrow = lrow + 64 * r;
                ra[r] = *(const float4*)(g_bmx + (size_t)(m0 + rrow) * C_DIM + k0 + 16 + lc4 * 4);
                rb[r] = *(const float4*)(fc1w + (size_t)(n0 + rrow) * C_DIM + k0 + 16 + lc4 * 4);
            }
        }
#pragma unroll
        for (int ks = 0; ks < 2; ks++) {
            const int kk = ks * 8;
            uint32_t ah[4][4], al[4][4], bh[4][2], bl[4][2];
#pragma unroll
            for (int mt = 0; mt < 4; mt++) {
                int mr = wm * 64 + mt * 16 + grp;
                ah[mt][0] = Ah[mr * SEL_ST + kk + tig];
                ah[mt][1] = Ah[(mr + 8) * SEL_ST + kk + tig];
                ah[mt][2] = Ah[mr * SEL_ST + kk + tig + 4];
                ah[mt][3] = Ah[(mr + 8) * SEL_ST + kk + tig + 4];
                al[mt][0] = Al[mr * SEL_ST + kk + tig];
                al[mt][1] = Al[(mr + 8) * SEL_ST + kk + tig];
                al[mt][2] = Al[mr * SEL_ST + kk + tig + 4];
                al[mt][3] = Al[(mr + 8) * SEL_ST + kk + tig + 4];
            }
#pragma unroll
            for (int nt = 0; nt < 4; nt++) {
                int nb = wn * 32 + nt * 8 + grp;
                bh[nt][0] = Bh[nb * SEL_ST + kk + tig];
                bh[nt][1] = Bh[nb * SEL_ST + kk + tig + 4];
                bl[nt][0] = Bl[nb * SEL_ST + kk + tig];
                bl[nt][1] = Bl[nb * SEL_ST + kk + tig + 4];
            }
#pragma unroll
            for (int mt = 0; mt < 4; mt++)
#pragma unroll
                for (int nt = 0; nt < 4; nt++) {
                    mma_frag(acc[mt][nt], ah[mt], bl[nt]);
                    mma_frag(acc[mt][nt], al[mt], bh[nt]);
                    mma_frag(acc[mt][nt], ah[mt], bh[nt]);
                }
        }
        __syncthreads();
    }
#pragma unroll
    for (int mt = 0; mt < 4; mt++)
#pragma unroll
        for (int nt = 0; nt < 4; nt++) {
            int m_l = wm * 64 + mt * 16 + grp;
            int n_l = wn * 32 + nt * 8 + tig * 2;
            S[n_l * 129 + m_l]           = acc[mt][nt][0];
            S[(n_l + 1) * 129 + m_l]     = acc[mt][nt][1];
            S[n_l * 129 + m_l + 8]       = acc[mt][nt][2];
            S[(n_l + 1) * 129 + m_l + 8] = acc[mt][nt][3];
        }
    __syncthreads();
    const int f_l = tid & 127, gh = tid >> 7;
    const int fg = n0 + f_l;
    const float bias = fc1b[fg];
#pragma unroll
    for (int q = 0; q < 8; q++) {
        int mb_l0 = (gh * 8 + q) * 8;
        float s = 0.f;
#pragma unroll
        for (int t = 0; t < 8; t++)
            s += fabsf(S[f_l * 129 + mb_l0 + t] + bias -
                       bmc[(size_t)(m0 + mb_l0 + t) * F_DIM + fg]);
        g_mdiff[(size_t)((m0 + mb_l0) >> 3) * F_DIM + fg] = s;
    }
#endif
}

// ---------------- kernel 3: parallel top-1536 (radix select) ----------------
__global__ __launch_bounds__(1024) void k_topk() {
    const int b = blockIdx.x, tid = threadIdx.x;
    const int lane = tid & 31, w = tid >> 5;
    const float* v = g_mdiff + (size_t)b * F_DIM;
    const int f0 = tid * 12;
    float vals[12];
#pragma unroll
    for (int j = 0; j < 12; j++) vals[j] = v[f0 + j];

    __shared__ int hist[256];
    __shared__ unsigned pref_s;
    __shared__ int rem_s;
    __shared__ int wsum[32];
    __shared__ int total_s;

    unsigned pref = 0;
    int rem = KSEL;
    for (int pass = 0; pass < 4; pass++) {
        const int sh = 24 - 8 * pass;
        if (tid < 256) hist[tid] = 0;
        __syncthreads();
#pragma unroll
        for (int j = 0; j < 12; j++) {
            unsigned u = __float_as_uint(vals[j]);
            if (pass == 0 || (u >> (sh + 8)) == pref)
                atomicAdd(&hist[(u >> sh) & 255], 1);
        }
        __syncthreads();
        for (int off = 1; off < 256; off <<= 1) {
            int x_;
            if (tid < 256) x_ = hist[tid] + ((tid + off < 256) ? hist[tid + off] : 0);
            __syncthreads();
            if (tid < 256) hist[tid] = x_;
            __syncthreads();
        }
        if (tid < 256) {
            int nxt = (tid == 255) ? 0 : hist[tid + 1];
            if (hist[tid] >= rem && nxt < rem) {
                pref_s = (pref << 8) | (unsigned)tid;
                rem_s = rem - nxt;
            }
        }
        __syncthreads();
        pref = pref_s;
        rem = rem_s;
        __syncthreads();
    }
    int cgt = 0, ceq = 0;
#pragma unroll
    for (int j = 0; j < 12; j++) {
        unsigned u = __float_as_uint(vals[j]);
        if (u > pref) cgt++;
        else if (u == pref) ceq++;
    }
    int inc = cgt;
#pragma unroll
    for (int off = 1; off < 32; off <<= 1) {
        int n_ = __shfl_up_sync(0xffffffffu, inc, off);
        if (lane >= off) inc += n_;
    }
    if (lane == 31) wsum[w] = inc;
    __syncthreads();
    if (w == 0) {
        int t = wsum[lane];
#pragma unroll
        for (int off = 1; off < 32; off <<= 1) {
            int n_ = __shfl_up_sync(0xffffffffu, t, off);
            if (lane >= off) t += n_;
        }
        wsum[lane] = t;
    }
    __syncthreads();
    int basep = (w > 0 ? wsum[w - 1] : 0) + inc - cgt;
    if (tid == 1023) total_s = basep + cgt;
    __syncthreads();
    const int total_gt = total_s;
    {
        int pos = basep;
#pragma unroll
        for (int j = 0; j < 12; j++)
            if (__float_as_uint(vals[j]) > pref) g_inds[b * KSEL + (pos++)] = f0 + j;
    }
    __syncthreads();
    inc = ceq;
#pragma unroll
    for (int off = 1; off < 32; off <<= 1) {
        int n_ = __shfl_up_sync(0xffffffffu, inc, off);
        if (lane >= off) inc += n_;
    }
    if (lane == 31) wsum[w] = inc;
    __syncthreads();
    if (w == 0) {
        int t = wsum[lane];
#pragma unroll
        for (int off = 1; off < 32; off <<= 1) {
            int n_ = __shfl_up_sync(0xffffffffu, t, off);
            if (lane >= off) t += n_;
        }
        wsum[lane] = t;
    }
    __syncthreads();
    int ebase = (w > 0 ? wsum[w - 1] : 0) + inc - ceq;
    const int need = KSEL - total_gt;
#pragma unroll
    for (int j = 0; j < 12; j++)
        if (__float_as_uint(vals[j]) == pref) {
            if (ebase < need) g_inds[b * KSEL + total_gt + ebase] = f0 + j;
            ebase++;
        }
}

#if TC_OK
// ---- shared epilogues ----
__device__ __forceinline__ void gemm1_epilogue(uint32_t tmem, const int* ridx,
                                               const float* bsh, const float* sAT,
                                               int blk, int mchunk, int tid) {
    const int wid = tid >> 5, lane = tid & 31;
    const int subp = wid & 3, tok = subp * 32 + lane;
    const int cb = (wid >> 2) * 64;
#pragma unroll
    for (int g = 0; g < 2; g++) {
        uint32_t d[32];
        TC_LD32(d, tmem + cb + g * 32);
        tc_wait_ld();
        uint32_t o[32];
#pragma unroll
        for (int j = 0; j < 32; j++) {
            int chl = cb + g * 32 + j;
            float vm = __uint_as_float(d[j]) + bsh[chl];
            float cached = sAT[(size_t)ridx[chl] * NTOK + blk * BM_ + tok];
            o[j] = f2tf(gelu_t(vm) - cached);
        }
        float* dp = g_delta + ((size_t)blk * BM_ + tok) * KSEL + mchunk * 128 + cb + g * 32;
#pragma unroll
        for (int q = 0; q < 8; q++) *(uint4*)(dp + q * 4) = *(uint4*)&o[q * 4];
    }
}
__device__ __forceinline__ void gemm2_epilogue(uint32_t tmem, const float* out_cache,
                                               float* out, int blk, int n0, int tid) {
    const int wid = tid >> 5, lane = tid & 31;
    const int subp = wid & 3, tok = subp * 32 + lane;
    const int cb = (wid >> 2) * 64;
#pragma unroll
    for (int g = 0; g < 2; g++) {
        uint32_t d[32];
        TC_LD32(d, tmem + cb + g * 32);
        tc_wait_ld();
        size_t off = (size_t)(blk * BM_ + tok) * C_DIM + n0 + cb + g * 32;
#pragma unroll
        for (int q = 0; q < 8; q++) {
            float4 oc = *(const float4*)(out_cache + off + q * 4);
            oc.x += __uint_as_float(d[q * 4 + 0]);
            oc.y += __uint_as_float(d[q * 4 + 1]);
            oc.z += __uint_as_float(d[q * 4 + 2]);
            oc.w += __uint_as_float(d[q * 4 + 3]);
            *(float4*)(out + off + q * 4) = oc;
        }
    }
}
#endif

// ---------------- kernel 4: gemm1 (R7: 3-stage cp.async) ----------------
__global__ __launch_bounds__(256) void k_gemm1(const float* __restrict__ x,
                                               const float* __restrict__ fc1w,
                                               const float* __restrict__ fc1b,
                                               const float* __restrict__ sAT) {
    extern __shared__ char dsm[];
    char* base = (char*)((((uintptr_t)dsm) + 1023) & ~(uintptr_t)1023);
    __shared__ int ridx[128];
    __shared__ float bsh[128];
    const int tid = threadIdx.x, wid = tid >> 5, lane = tid & 31;
    const int blk = blockIdx.y, mchunk = blockIdx.x;

#if TC_OK
    __shared__ uint32_t s_tmem;
    __shared__ uint64_t s_mbar[3];
    const uint32_t sb = sm32(base);

    if (wid == 0) { tc_alloc(sm32(&s_tmem), 128); tc_relinq(); }
    if (tid == 0)
        for (int q = 0; q < 3; q++) mbar_init(sm32(&s_mbar[q]), 1);
    if (tid < 128) {
        int id = g_inds[blk * KSEL + mchunk * 128 + tid];
        ridx[tid] = id;
        bsh[tid] = fc1b[id];
    }
    __syncthreads();
    const uint32_t tmem = s_tmem;
    uint32_t mbx[3] = {sm32(&s_mbar[0]), sm32(&s_mbar[1]), sm32(&s_mbar[2])};

    const float* xb = g_xr + (size_t)blk * BM_ * C_DIM;
    const int row = tid >> 3, c4 = tid & 7;
    const int NCH = C_DIM / 32;
#pragma unroll
    for (int j = 0; j < 3; j++) {
        const uint32_t At = sb + (j * 2 + 0) * 16384, Bt = sb + (j * 2 + 1) * 16384;
        int k0 = j * 32;
#pragma unroll
        for (int r = 0; r < 4; r++) {
            int rr = row + 32 * r;
            cp16(At + SWZ(rr * 128 + c4 * 16), xb + (size_t)rr * C_DIM + k0 + c4 * 4);
            cp16(Bt + SWZ(rr * 128 + c4 * 16), fc1w + (size_t)ridx[rr] * C_DIM + k0 + c4 * 4);
        }
        cp_commit();
    }
    for (int i = 0; i < NCH; i++) {
        const int b = i % 3;
        if (i < NCH - 2)      cp_wait<2>();
        else if (i == NCH - 2) cp_wait<1>();
        else                   cp_wait<0>();
        fence_async();
        __syncthreads();
        const uint32_t At = sb + (b * 2 + 0) * 16384, Bt = sb + (b * 2 + 1) * 16384;
        if (tid == 0) {
            uint64_t da = mk_desc(At), db = mk_desc(Bt);
#pragma unroll
            for (int ks = 0; ks < 4; ks++)
                mma_ss(tmem, da + ks * 2, db + ks * 2, (i | ks) ? 1u : 0u);
            tc_commit(mbx[b]);
        }
        if (i + 3 < NCH) {
            mbar_wait(mbx[b], (i / 3) & 1);
            int k0 = (i + 3) * 32;
#pragma unroll
            for (int r = 0; r < 4; r++) {
                int rr = row + 32 * r;
                cp16(At + SWZ(rr * 128 + c4 * 16), xb + (size_t)rr * C_DIM + k0 + c4 * 4);
                cp16(Bt + SWZ(rr * 128 + c4 * 16), fc1w + (size_t)ridx[rr] * C_DIM + k0 + c4 * 4);
            }
            cp_commit();
        }
    }
    mbar_wait(mbx[(NCH - 1) % 3], ((NCH - 1) / 3) & 1);
    tc_fence_after();
    gemm1_epilogue(tmem, ridx, bsh, sAT, blk, mchunk, tid);
    __syncthreads();
    if (wid == 0) tc_dealloc(tmem, 128);

#else
    // fallback: mma.sync, C[ch][tok], delta stored [blk][ch][tok]
    const int G1_ST = 36;
    uint32_t* As = (uint32_t*)base;
    uint32_t* Bs = As + 128 * G1_ST;
    const int wm = wid & 1, wn = wid >> 1;
    const int grp = lane >> 2, tig = lane & 3;

    if (tid < 128) {
        int id = g_inds[blk * KSEL + mchunk * 128 + tid];
        ridx[tid] = id;
        bsh[tid] = fc1b[id];
    }
    __syncthreads();
    float acc[4][4][4];
#pragma unroll
    for (int i = 0; i < 4; i++)
#pragma unroll
        for (int j = 0; j < 4; j++)
#pragma unroll
            for (int q = 0; q < 4; q++) acc[i][j][q] = 0.f;

    const float* xb = x + (size_t)blk * BM_ * C_DIM;
    const int lrow = tid >> 3, lc4 = tid & 7;
    float4 ra[4], rb[4];
#pragma unroll
    for (int r = 0; r < 4; r++) {
        int rrow = lrow + 32 * r;
        ra[r] = *(const float4*)(fc1w + (size_t)ridx[rrow] * C_DIM + lc4 * 4);
        rb[r] = *(const float4*)(xb + (size_t)rrow * C_DIM + lc4 * 4);
    }
    for (int k0 = 0; k0 < C_DIM; k0 += 32) {
#pragma unroll
        for (int r = 0; r < 4; r++) {
            int rrow = lrow + 32 * r;
            int bidx = rrow * G1_ST + lc4 * 4;
            As[bidx + 0] = f2tf(ra[r].x); As[bidx + 1] = f2tf(ra[r].y);
            As[bidx + 2] = f2tf(ra[r].z); As[bidx + 3] = f2tf(ra[r].w);
            Bs[bidx + 0] = f2tf(rb[r].x); Bs[bidx + 1] = f2tf(rb[r].y);
            Bs[bidx + 2] = f2tf(rb[r].z); Bs[bidx + 3] = f2tf(rb[r].w);
        }
        __syncthreads();
        if (k0 + 32 < C_DIM) {
#pragma unroll
            for (int r = 0; r < 4; r++) {
                int rrow = lrow + 32 * r;
                ra[r] = *(const float4*)(fc1w + (size_t)ridx[rrow] * C_DIM + k0 + 32 + lc4 * 4);
                rb[r] = *(const float4*)(xb + (size_t)rrow * C_DIM + k0 + 32 + lc4 * 4);
            }
        }
#pragma unroll
        for (int ks = 0; ks < 4; ks++) {
            const int kk = ks * 8;
            uint32_t af[4][4], bf[4][2];
#pragma unroll
            for (int mt = 0; mt < 4; mt++) {
                int mr = wm * 64 + mt * 16 + grp;
                af[mt][0] = As[mr * G1_ST + kk + tig];
                af[mt][1] = As[(mr + 8) * G1_ST + kk + tig];
                af[mt][2] = As[mr * G1_ST + kk + tig + 4];
                af[mt][3] = As[(mr + 8) * G1_ST + kk + tig + 4];
            }
#pragma unroll
            for (int nt = 0; nt < 4; nt++) {
                int nb = wn * 32 + nt * 8 + grp;
                bf[nt][0] = Bs[nb * G1_ST + kk + tig];
                bf[nt][1] = Bs[nb * G1_ST + kk + tig + 4];
            }
#pragma unroll
            for (int mt = 0; mt < 4; mt++)
#pragma unroll
                for (int nt = 0; nt < 4; nt++) mma_frag(acc[mt][nt], af[mt], bf[nt]);
        }
        __syncthreads();
    }
#pragma unroll
    for (int mt = 0; mt < 4; mt++)
#pragma unroll
        for (int nt = 0; nt < 4; nt++) {
            int t0 = wn * 32 + nt * 8 + tig * 2;
#pragma unroll
            for (int half = 0; half < 2; half++) {
                int r = wm * 64 + mt * 16 + grp + 8 * half;
                float bb = bsh[r];
                int chg = ridx[r];
                const float* cp = sAT + (size_t)chg * NTOK + blk * BM_ + t0;
                float2 cached = *(const float2*)cp;
                float v0 = acc[mt][nt][half * 2 + 0] + bb;
                float v1 = acc[mt][nt][half * 2 + 1] + bb;
                float2 o;
                o.x = gelu_t(v0) - cached.x;
                o.y = gelu_t(v1) - cached.y;
                *(float2*)(g_delta + ((size_t)blk * KSEL + mchunk * 128 + r) * BM_ + t0) = o;
            }
        }
#endif
}

// ---------------- kernel 5: gemm2 (R7: 3-stage cp.async, cp4 B transpose) ----------------
__global__ __launch_bounds__(256) void k_gemm2(const float* __restrict__ fc2wT,
                                               const float* __restrict__ out_cache,
                                               float* __restrict__ out) {
    extern __shared__ char dsm[];
    char* base = (char*)((((uintptr_t)dsm) + 1023) & ~(uintptr_t)1023);
    __shared__ int kid[KSEL];
    const int tid = threadIdx.x, wid = tid >> 5, lane = tid & 31;
    const int blk = blockIdx.y, n0 = blockIdx.x * 128;

#if TC_OK
    __shared__ uint32_t s_tmem;
    __shared__ uint64_t s_mbar[3];
    const uint32_t sb = sm32(base);

    if (wid == 0) { tc_alloc(sm32(&s_tmem), 128); tc_relinq(); }
    if (tid == 0)
        for (int q = 0; q < 3; q++) mbar_init(sm32(&s_mbar[q]), 1);
    for (int i = tid; i < KSEL; i += 256) kid[i] = g_inds[blk * KSEL + i];
    __syncthreads();
    const uint32_t tmem = s_tmem;
    uint32_t mbx[3] = {sm32(&s_mbar[0]), sm32(&s_mbar[1]), sm32(&s_mbar[2])};

    const float* Ab = g_delta + (size_t)blk * BM_ * KSEL;
    const int row = tid >> 3, c4 = tid & 7;
    const int cB = tid & 127, ch4b = tid >> 7;
    const int NCH = KSEL / 32;  // 48
#pragma unroll
    for (int j = 0; j < 3; j++) {
        const uint32_t At = sb + (j * 2 + 0) * 16384, Bt = sb + (j * 2 + 1) * 16384;
        int k0 = j * 32;
#pragma unroll
        for (int r = 0; r < 4; r++) {
            int rr = row + 32 * r;
            cp16(At + SWZ(rr * 128 + c4 * 16), Ab + (size_t)rr * KSEL + k0 + c4 * 4);
        }
#pragma unroll
        for (int jj = 0; jj < 4; jj++) {
            int ch4 = ch4b + jj * 2;
            uint32_t db = Bt + SWZ(cB * 128 + ch4 * 16);
#pragma unroll
            for (int q = 0; q < 4; q++)
                cp4(db + q * 4, fc2wT + (size_t)kid[k0 + ch4 * 4 + q] * C_DIM + n0 + cB);
        }
        cp_commit();
    }
    for (int i = 0; i < NCH; i++) {
        const int b = i % 3;
        if (i < NCH - 2)      cp_wait<2>();
        else if (i == NCH - 2) cp_wait<1>();
        else                   cp_wait<0>();
        fence_async();
        __syncthreads();
        const uint32_t At = sb + (b * 2 + 0) * 16384, Bt = sb + (b * 2 + 1) * 16384;
        if (tid == 0) {
            uint64_t da = mk_desc(At), db = mk_desc(Bt);
#pragma unroll
            for (int ks = 0; ks < 4; ks++)
                mma_ss(tmem, da + ks * 2, db + ks * 2, (i | ks) ? 1u : 0u);
            tc_commit(mbx[b]);
        }
        if (i + 3 < NCH) {
            mbar_wait(mbx[b], (i / 3) & 1);
            int k0 = (i + 3) * 32;
#pragma unroll
            for (int r = 0; r < 4; r++) {
                int rr = row + 32 * r;
                cp16(At + SWZ(rr * 128 + c4 * 16), Ab + (size_t)rr * KSEL + k0 + c4 * 4);
            }
#pragma unroll
            for (int jj = 0; jj < 4; jj++) {
                int ch4 = ch4b + jj * 2;
                uint32_t db = Bt + SWZ(cB * 128 + ch4 * 16);
#pragma unroll
                for (int q = 0; q < 4; q++)
                    cp4(db + q * 4, fc2wT + (size_t)kid[k0 + ch4 * 4 + q] * C_DIM + n0 + cB);
            }
            cp_commit();
        }
    }
    mbar_wait(mbx[(NCH - 1) % 3], ((NCH - 1) / 3) & 1);
    tc_fence_after();
    gemm2_epilogue(tmem, out_cache, out, blk, n0, tid);
    __syncthreads();
    if (wid == 0) tc_dealloc(tmem, 128);

#else
    const int G2_ST = 136;
    uint32_t* As = (uint32_t*)base;
    uint32_t* Bs = As + 32 * G2_ST;
    const int wm = wid & 1, wn = wid >> 1;
    const int grp = lane >> 2, tig = lane & 3;

    for (int i = tid; i < KSEL; i += 256) kid[i] = g_inds[blk * KSEL + i];
    __syncthreads();

    float acc[4][4][4];
#pragma unroll
    for (int i = 0; i < 4; i++)
#pragma unroll
        for (int j = 0; j < 4; j++)
#pragma unroll
            for (int q = 0; q < 4; q++) acc[i][j][q] = 0.f;

    const float* Ab = g_delta + (size_t)blk * KSEL * BM_;
    float4 ra[4], rb[4];
#pragma unroll
    for (int r = 0; r < 4; r++) {
        int idx = tid + 256 * r;
        int ch = idx >> 5, t4 = idx & 31;
        ra[r] = *(const float4*)(Ab + (size_t)ch * BM_ + t4 * 4);
        rb[r] = *(const float4*)(fc2wT + (size_t)kid[ch] * C_DIM + n0 + t4 * 4);
    }
    for (int k0 = 0; k0 < KSEL; k0 += 32) {
#pragma unroll
        for (int r = 0; r < 4; r++) {
            int idx = tid + 256 * r;
            int ch = idx >> 5, t4 = idx & 31;
            int bidx = ch * G2_ST + t4 * 4;
            As[bidx + 0] = f2tf(ra[r].x); As[bidx + 1] = f2tf(ra[r].y);
            As[bidx + 2] = f2tf(ra[r].z); As[bidx + 3] = f2tf(ra[r].w);
            Bs[bidx + 0] = f2tf(rb[r].x); Bs[bidx + 1] = f2tf(rb[r].y);
            Bs[bidx + 2] = f2tf(rb[r].z); Bs[bidx + 3] = f2tf(rb[r].w);
        }
        __syncthreads();
        if (k0 + 32 < KSEL) {
#pragma unroll
            for (int r = 0; r < 4; r++) {
                int idx = tid + 256 * r;
                int ch = idx >> 5, t4 = idx & 31;
                ra[r] = *(const float4*)(Ab + (size_t)(k0 + 32 + ch) * BM_ + t4 * 4);
                rb[r] = *(const float4*)(fc2wT + (size_t)kid[k0 + 32 + ch] * C_DIM + n0 + t4 * 4);
            }
        }
#pragma unroll
        for (int ks = 0; ks < 4; ks++) {
            const int kk = ks * 8;
            uint32_t af[4][4], bf[4][2];
#pragma unroll
            for (int mt = 0; mt < 4; mt++) {
                int mbr = wm * 64 + mt * 16 + grp;
                af[mt][0] = As[(kk + tig) * G2_ST + mbr];
                af[mt][1] = As[(kk + tig) * G2_ST + mbr + 8];
                af[mt][2] = As[(kk + tig + 4) * G2_ST + mbr];
                af[mt][3] = As[(kk + tig + 4) * G2_ST + mbr + 8];
            }
#pragma unroll
            for (int nt = 0; nt < 4; nt++) {
                int nb = wn * 32 + nt * 8 + grp;
                bf[nt][0] = Bs[(kk + tig) * G2_ST + nb];
                bf[nt][1] = Bs[(kk + tig + 4) * G2_ST + nb];
            }
#pragma unroll
            for (int mt = 0; mt < 4; mt++)
#pragma unroll
                for (int nt = 0; nt < 4; nt++) mma_frag(acc[mt][nt], af[mt], bf[nt]);
        }
        __syncthreads();
    }
#pragma unroll
    for (int mt = 0; mt < 4; mt++)
#pragma unroll
        for (int nt = 0; nt < 4; nt++) {
            int col = n0 + wn * 32 + nt * 8 + tig * 2;
#pragma unroll
            for (int half = 0; half < 2; half++) {
                int trow = wm * 64 + mt * 16 + grp + 8 * half;
                size_t off = (size_t)(blk * BM_ + trow) * C_DIM + col;
                float2 oc = *(const float2*)(out_cache + off);
                float2 o;
                o.x = oc.x + acc[mt][nt][half * 2 + 0];
                o.y = oc.y + acc[mt][nt][half * 2 + 1];
                *(float2*)(out + off) = o;
            }
        }
#endif
}

// ---------------- launch (serial, R7) ----------------
extern "C" void kernel_launch(void* const* d_in, const int* in_sizes, int n_in,
                              void* d_out, int out_size) {
    const float* x     = (const float*)d_in[0];
    const float* fc1w  = (const float*)d_in[1];
    const float* fc1b  = (const float*)d_in[2];
    const float* fc2wT = (const float*)d_in[3];
    const float* bmc   = (const float*)d_in[4];
    const float* sAT   = (const float*)d_in[5];
    const float* outc  = (const float*)d_in[6];
    float* out = (float*)d_out;

    cudaFuncSetAttribute(k_sel,   cudaFuncAttributeMaxDynamicSharedMemorySize, SEL_SMEM);
    cudaFuncSetAttribute(k_gemm1, cudaFuncAttributeMaxDynamicSharedMemorySize, G_SMEM);
    cudaFuncSetAttribute(k_gemm2, cudaFuncAttributeMaxDynamicSharedMemorySize, G_SMEM);

    k_xr<<<NTOK * C_DIM / 1024, 256>>>(x);
    k_bmean<<<dim3(256, 6), 512>>>(x);
    k_sel<<<dim3(96, 2), 256, SEL_SMEM>>>(fc1w, fc1b, bmc);
    k_topk<<<32, 1024>>>();
    k_gemm1<<<dim3(12, 32), 256, G_SMEM>>>(x, fc1w, fc1b, sAT);
    k_gemm2<<<dim3(24, 32), 256, G_SMEM>>>(fc2wT, outc, out);
}

// round 17
// speedup vs baseline: 1.6818x; 1.2692x over previous
#include <cuda_runtime.h>
#include <cstdint>

#if defined(__CUDA_ARCH_FEAT_SM103_ALL) || defined(__CUDA_ARCH_FEAT_SM100_ALL) || \
    (defined(__CUDA_ARCH_FAMILY_SPECIFIC__) && (__CUDA_ARCH_FAMILY_SPECIFIC__ >= 1000))
#define TC_OK 1
#else
#define TC_OK 0
#endif

#define NTOK 4096
#define C_DIM 3072
#define F_DIM 12288
#define NB 32
#define BM_ 128
#define MBM_ 16
#define MBS 256
#define KSEL 1536

// idesc: dtype F32(1<<4), atype TF32(2<<7), btype TF32(2<<10), N=128(16<<17), M=128(8<<24)
#define IDESC_TF32 ((1u<<4)|(2u<<7)|(2u<<10)|(16u<<17)|(8u<<24))
#define SWZ(o) ((o) ^ (((o) >> 3) & 0x70))

#define SEL_SMEM (4 * 16384 + 1024)   // single stage: Ah Al Bh Bl (3 CTAs/SM)
#define G_SMEM   (2 * 16384 + 1024)   // single stage: A 16KB + B 16KB (4 CTAs/SM)

// ---------------- scratch ----------------
__device__ float g_bmx[MBS * C_DIM];
__device__ float g_mdiff[NB * F_DIM];
__device__ int   g_inds[NB * KSEL];
__device__ float g_delta[(size_t)NB * BM_ * KSEL];   // [blk][tok][ch], tf32-RNA rounded
__device__ float g_xr[(size_t)NTOK * C_DIM];         // x pre-rounded to tf32-RNA

// ---------------- common helpers ----------------
__device__ __forceinline__ uint32_t f2tf(float x) {
    uint32_t u; asm("cvt.rna.tf32.f32 %0, %1;" : "=r"(u) : "f"(x)); return u;
}
__device__ __forceinline__ float gelu_t(float v) {
    return 0.5f * v * (1.f + tanhf(0.7978845608028654f * (v + 0.044715f * v * v * v)));
}
__device__ __forceinline__ void mma_frag(float c[4], const uint32_t a[4], const uint32_t b[2]) {
    asm volatile(
        "mma.sync.aligned.m16n8k8.row.col.f32.tf32.tf32.f32 "
        "{%0,%1,%2,%3},{%4,%5,%6,%7},{%8,%9},{%0,%1,%2,%3};"
        : "+f"(c[0]), "+f"(c[1]), "+f"(c[2]), "+f"(c[3])
        : "r"(a[0]), "r"(a[1]), "r"(a[2]), "r"(a[3]), "r"(b[0]), "r"(b[1]));
}

#if TC_OK
__device__ __forceinline__ uint32_t sm32(const void* p) {
    uint32_t a;
    asm("{ .reg .u64 t; cvta.to.shared.u64 t, %1; cvt.u32.u64 %0, t; }" : "=r"(a) : "l"(p));
    return a;
}
__device__ __forceinline__ void mbar_init(uint32_t m, uint32_t c) {
    asm volatile("mbarrier.init.shared.b64 [%0], %1;" :: "r"(m), "r"(c) : "memory");
}
__device__ __forceinline__ void mbar_wait(uint32_t m, uint32_t par) {
    asm volatile(
        "{\n\t.reg .pred P;\n"
        "W_%=:\n\t"
        "mbarrier.try_wait.parity.acquire.cta.shared::cta.b64 P, [%0], %1, 0x989680;\n\t"
        "@!P bra.uni W_%=;\n\t}"
        :: "r"(m), "r"(par) : "memory");
}
__device__ __forceinline__ void tc_alloc(uint32_t slot, uint32_t n) {
    asm volatile("tcgen05.alloc.cta_group::1.sync.aligned.shared::cta.b32 [%0], %1;"
                 :: "r"(slot), "r"(n) : "memory");
}
__device__ __forceinline__ void tc_relinq() {
    asm volatile("tcgen05.relinquish_alloc_permit.cta_group::1.sync.aligned;");
}
__device__ __forceinline__ void tc_dealloc(uint32_t t, uint32_t n) {
    asm volatile("tcgen05.dealloc.cta_group::1.sync.aligned.b32 %0, %1;" :: "r"(t), "r"(n));
}
__device__ __forceinline__ void tc_commit(uint32_t m) {
    asm volatile("tcgen05.commit.cta_group::1.mbarrier::arrive::one.shared::cluster.b64 [%0];"
                 :: "r"(m) : "memory");
}
__device__ __forceinline__ void fence_async() {
    asm volatile("fence.proxy.async.shared::cta;" ::: "memory");
}
__device__ __forceinline__ void tc_fence_after() {
    asm volatile("tcgen05.fence::after_thread_sync;" ::: "memory");
}
__device__ __forceinline__ void tc_wait_ld() {
    asm volatile("tcgen05.wait::ld.sync.aligned;" ::: "memory");
}
__device__ __forceinline__ void mma_ss(uint32_t d, uint64_t a, uint64_t b, uint32_t en) {
    asm volatile(
        "{\n\t.reg .pred p;\n\t"
        "setp.ne.u32 p, %5, 0;\n\t"
        "tcgen05.mma.cta_group::1.kind::tf32 [%0], %1, %2, %3, {%4,%4,%4,%4}, p;\n\t}"
        :: "r"(d), "l"(a), "l"(b), "r"(IDESC_TF32), "r"(0u), "r"(en) : "memory");
}
__device__ __forceinline__ uint64_t mk_desc(uint32_t addr) {
    const uint64_t base = (uint64_t(2) << 61) | (uint64_t(1) << 46) |
                          (uint64_t(64) << 32) | (uint64_t(1) << 16);
    return base | ((uint64_t)(addr >> 4) & 0x3FFF);
}
#define TC_LD32(r, a) \
    asm volatile( \
        "tcgen05.ld.sync.aligned.32x32b.x32.b32 " \
        "{%0,%1,%2,%3,%4,%5,%6,%7,%8,%9,%10,%11,%12,%13,%14,%15," \
        "%16,%17,%18,%19,%20,%21,%22,%23,%24,%25,%26,%27,%28,%29,%30,%31}, [%32];" \
        : "=r"((r)[0]),"=r"((r)[1]),"=r"((r)[2]),"=r"((r)[3]),"=r"((r)[4]),"=r"((r)[5]), \
          "=r"((r)[6]),"=r"((r)[7]),"=r"((r)[8]),"=r"((r)[9]),"=r"((r)[10]),"=r"((r)[11]), \
          "=r"((r)[12]),"=r"((r)[13]),"=r"((r)[14]),"=r"((r)[15]),"=r"((r)[16]),"=r"((r)[17]), \
          "=r"((r)[18]),"=r"((r)[19]),"=r"((r)[20]),"=r"((r)[21]),"=r"((r)[22]),"=r"((r)[23]), \
          "=r"((r)[24]),"=r"((r)[25]),"=r"((r)[26]),"=r"((r)[27]),"=r"((r)[28]),"=r"((r)[29]), \
          "=r"((r)[30]),"=r"((r)[31]) : "r"(a))
#endif  // TC_OK

// ---------------- kernel 0: pre-round x to tf32 RNA ----------------
__global__ void k_xr(const float* __restrict__ x) {
    size_t i = (size_t)blockIdx.x * 256 + threadIdx.x;
    float4 v = ((const float4*)x)[i];
    uint4 o;
    asm("cvt.rna.tf32.f32 %0, %1;" : "=r"(o.x) : "f"(v.x));
    asm("cvt.rna.tf32.f32 %0, %1;" : "=r"(o.y) : "f"(v.y));
    asm("cvt.rna.tf32.f32 %0, %1;" : "=r"(o.z) : "f"(v.z));
    asm("cvt.rna.tf32.f32 %0, %1;" : "=r"(o.w) : "f"(v.w));
    ((uint4*)g_xr)[i] = o;
}

// ---------------- kernel 1: block means ----------------
__global__ void k_bmean(const float* __restrict__ x) {
    int mb = blockIdx.x;
    int c  = blockIdx.y * 512 + threadIdx.x;
    const float* p = x + (size_t)mb * MBM_ * C_DIM + c;
    float s = 0.f;
#pragma unroll
    for (int t = 0; t < MBM_; t++) s += p[(size_t)t * C_DIM];
    g_bmx[mb * C_DIM + c] = s * (1.f / 16.f);
}

// ---------------- kernel 2: selection GEMM (3xTF32), single-stage (3 CTAs/SM) -----------
__global__ __launch_bounds__(256, 3) void k_sel(const float* __restrict__ fc1w,
                                                const float* __restrict__ fc1b,
                                                const float* __restrict__ bmc) {
    extern __shared__ char dsm[];
    char* base = (char*)((((uintptr_t)dsm) + 1023) & ~(uintptr_t)1023);
    const int tid = threadIdx.x, wid = tid >> 5, lane = tid & 31;

#if TC_OK
    __shared__ uint32_t s_tmem;
    __shared__ uint64_t s_mbar;
    const int m0 = blockIdx.x * 128, n0 = blockIdx.y * 128;
    const uint32_t sb = sm32(base);

    if (wid == 0) { tc_alloc(sm32(&s_tmem), 128); tc_relinq(); }
    if (tid == 0) mbar_init(sm32(&s_mbar), 1);
    __syncthreads();
    const uint32_t tmem = s_tmem;
    const uint32_t mb0 = sm32(&s_mbar);

    const uint32_t Ah = sb, Al = sb + 16384, Bh = sb + 32768, Bl = sb + 49152;

    const int row = tid >> 3, c4 = tid & 7;
    float4 ra[4], rb[4];
#pragma unroll
    for (int r = 0; r < 4; r++) {
        int rr = row + 32 * r;
        ra[r] = *(const float4*)(fc1w + (size_t)(m0 + rr) * C_DIM + c4 * 4);
        rb[r] = *(const float4*)(g_bmx + (size_t)(n0 + rr) * C_DIM + c4 * 4);
    }
    const int NCH = C_DIM / 32;  // 96
    for (int i = 0; i < NCH; i++) {
        if (i >= 1) mbar_wait(mb0, (i - 1) & 1);
#pragma unroll
        for (int r = 0; r < 4; r++) {
            int rr = row + 32 * r;
            uint32_t off = SWZ(rr * 128 + c4 * 16);
            float av[4] = {ra[r].x, ra[r].y, ra[r].z, ra[r].w};
            float bv[4] = {rb[r].x, rb[r].y, rb[r].z, rb[r].w};
            uint4 h, l;
            h.x = f2tf(av[0]); l.x = f2tf(av[0] - __uint_as_float(h.x));
            h.y = f2tf(av[1]); l.y = f2tf(av[1] - __uint_as_float(h.y));
            h.z = f2tf(av[2]); l.z = f2tf(av[2] - __uint_as_float(h.z));
            h.w = f2tf(av[3]); l.w = f2tf(av[3] - __uint_as_float(h.w));
            *(uint4*)(base + (Ah - sb) + off) = h;
            *(uint4*)(base + (Al - sb) + off) = l;
            h.x = f2tf(bv[0]); l.x = f2tf(bv[0] - __uint_as_float(h.x));
            h.y = f2tf(bv[1]); l.y = f2tf(bv[1] - __uint_as_float(h.y));
            h.z = f2tf(bv[2]); l.z = f2tf(bv[2] - __uint_as_float(h.z));
            h.w = f2tf(bv[3]); l.w = f2tf(bv[3] - __uint_as_float(h.w));
            *(uint4*)(base + (Bh - sb) + off) = h;
            *(uint4*)(base + (Bl - sb) + off) = l;
        }
        fence_async();
        if (i + 1 < NCH) {
            int k0 = (i + 1) * 32;
#pragma unroll
            for (int r = 0; r < 4; r++) {
                int rr = row + 32 * r;
                ra[r] = *(const float4*)(fc1w + (size_t)(m0 + rr) * C_DIM + k0 + c4 * 4);
                rb[r] = *(const float4*)(g_bmx + (size_t)(n0 + rr) * C_DIM + k0 + c4 * 4);
            }
        }
        __syncthreads();
        if (tid == 0) {
            uint64_t dah = mk_desc(Ah), dal = mk_desc(Al);
            uint64_t dbh = mk_desc(Bh), dbl = mk_desc(Bl);
#pragma unroll
            for (int ks = 0; ks < 4; ks++) {
                mma_ss(tmem, dah + ks * 2, dbl + ks * 2, (i | ks) ? 1u : 0u);
                mma_ss(tmem, dal + ks * 2, dbh + ks * 2, 1u);
                mma_ss(tmem, dah + ks * 2, dbh + ks * 2, 1u);
            }
            tc_commit(mb0);
        }
    }
    mbar_wait(mb0, (NCH - 1) & 1);   // chunk 95 done: parity 1
    tc_fence_after();
    const int subp = wid & 3, l = subp * 32 + lane;
    const int f = m0 + l;
    const float bias = fc1b[f];
    const int cb = (wid >> 2) * 64;
    float sum[8];
#pragma unroll
    for (int q = 0; q < 8; q++) sum[q] = 0.f;
#pragma unroll
    for (int g = 0; g < 2; g++) {
        uint32_t d[32];
        TC_LD32(d, tmem + cb + g * 32);
        tc_wait_ld();
#pragma unroll
        for (int j = 0; j < 32; j++) {
            int mbi = n0 + cb + g * 32 + j;
            float val = __uint_as_float(d[j]) + bias;
            sum[(g * 32 + j) >> 3] += fabsf(val - bmc[(size_t)mbi * F_DIM + f]);
        }
    }
    const int b0 = (n0 + cb) >> 3;
#pragma unroll
    for (int q = 0; q < 8; q++) g_mdiff[(size_t)(b0 + q) * F_DIM + f] = sum[q];
    __syncthreads();
    if (wid == 0) tc_dealloc(tmem, 128);

#else
    // fallback (dead on GB300): minimal correct path using smem budget is not provided;
    // retain compilable mma.sync path writing via registers without extra smem.
    const int m0 = blockIdx.y * 128, n0 = blockIdx.x * 128;
    (void)base; (void)wid; (void)lane;
    // simple scalar fallback: each thread computes 96 outputs of mdiff directly (slow, correct)
    for (int f_l = tid; f_l < 128; f_l += 256) {
        int fg = n0 + f_l;
        float bias = fc1b[fg];
        for (int mb_l = 0; mb_l < 128; mb_l += 8) {
            int b = (m0 + mb_l) >> 3;
            float s = 0.f;
            for (int t = 0; t < 8; t++) {
                const float* xr = g_bmx + (size_t)(m0 + mb_l + t) * C_DIM;
                const float* wr = fc1w + (size_t)fg * C_DIM;
                float acc = 0.f;
                for (int k = 0; k < C_DIM; k++) acc += xr[k] * wr[k];
                s += fabsf(acc + bias - bmc[(size_t)(m0 + mb_l + t) * F_DIM + fg]);
            }
            g_mdiff[(size_t)b * F_DIM + fg] = s;
        }
    }
#endif
}

// ---------------- kernel 3: parallel top-1536 (radix select) ----------------
__global__ __launch_bounds__(1024) void k_topk() {
    const int b = blockIdx.x, tid = threadIdx.x;
    const int lane = tid & 31, w = tid >> 5;
    const float* v = g_mdiff + (size_t)b * F_DIM;
    const int f0 = tid * 12;
    float vals[12];
#pragma unroll
    for (int j = 0; j < 12; j++) vals[j] = v[f0 + j];

    __shared__ int hist[256];
    __shared__ unsigned pref_s;
    __shared__ int rem_s;
    __shared__ int wsum[32];
    __shared__ int total_s;

    unsigned pref = 0;
    int rem = KSEL;
    for (int pass = 0; pass < 4; pass++) {
        const int sh = 24 - 8 * pass;
        if (tid < 256) hist[tid] = 0;
        __syncthreads();
#pragma unroll
        for (int j = 0; j < 12; j++) {
            unsigned u = __float_as_uint(vals[j]);
            if (pass == 0 || (u >> (sh + 8)) == pref)
                atomicAdd(&hist[(u >> sh) & 255], 1);
        }
        __syncthreads();
        for (int off = 1; off < 256; off <<= 1) {
            int x_;
            if (tid < 256) x_ = hist[tid] + ((tid + off < 256) ? hist[tid + off] : 0);
            __syncthreads();
            if (tid < 256) hist[tid] = x_;
            __syncthreads();
        }
        if (tid < 256) {
            int nxt = (tid == 255) ? 0 : hist[tid + 1];
            if (hist[tid] >= rem && nxt < rem) {
                pref_s = (pref << 8) | (unsigned)tid;
                rem_s = rem - nxt;
            }
        }
        __syncthreads();
        pref = pref_s;
        rem = rem_s;
        __syncthreads();
    }
    int cgt = 0, ceq = 0;
#pragma unroll
    for (int j = 0; j < 12; j++) {
        unsigned u = __float_as_uint(vals[j]);
        if (u > pref) cgt++;
        else if (u == pref) ceq++;
    }
    int inc = cgt;
#pragma unroll
    for (int off = 1; off < 32; off <<= 1) {
        int n_ = __shfl_up_sync(0xffffffffu, inc, off);
        if (lane >= off) inc += n_;
    }
    if (lane == 31) wsum[w] = inc;
    __syncthreads();
    if (w == 0) {
        int t = wsum[lane];
#pragma unroll
        for (int off = 1; off < 32; off <<= 1) {
            int n_ = __shfl_up_sync(0xffffffffu, t, off);
            if (lane >= off) t += n_;
        }
        wsum[lane] = t;
    }
    __syncthreads();
    int basep = (w > 0 ? wsum[w - 1] : 0) + inc - cgt;
    if (tid == 1023) total_s = basep + cgt;
    __syncthreads();
    const int total_gt = total_s;
    {
        int pos = basep;
#pragma unroll
        for (int j = 0; j < 12; j++)
            if (__float_as_uint(vals[j]) > pref) g_inds[b * KSEL + (pos++)] = f0 + j;
    }
    __syncthreads();
    inc = ceq;
#pragma unroll
    for (int off = 1; off < 32; off <<= 1) {
        int n_ = __shfl_up_sync(0xffffffffu, inc, off);
        if (lane >= off) inc += n_;
    }
    if (lane == 31) wsum[w] = inc;
    __syncthreads();
    if (w == 0) {
        int t = wsum[lane];
#pragma unroll
        for (int off = 1; off < 32; off <<= 1) {
            int n_ = __shfl_up_sync(0xffffffffu, t, off);
            if (lane >= off) t += n_;
        }
        wsum[lane] = t;
    }
    __syncthreads();
    int ebase = (w > 0 ? wsum[w - 1] : 0) + inc - ceq;
    const int need = KSEL - total_gt;
#pragma unroll
    for (int j = 0; j < 12; j++)
        if (__float_as_uint(vals[j]) == pref) {
            if (ebase < need) g_inds[b * KSEL + total_gt + ebase] = f0 + j;
            ebase++;
        }
}

#if TC_OK
// ---- shared epilogues ----
__device__ __forceinline__ void gemm1_epilogue(uint32_t tmem, const int* ridx,
                                               const float* bsh, const float* sAT,
                                               int blk, int mchunk, int tid) {
    const int wid = tid >> 5, lane = tid & 31;
    const int subp = wid & 3, tok = subp * 32 + lane;
    const int cb = (wid >> 2) * 64;
#pragma unroll
    for (int g = 0; g < 2; g++) {
        uint32_t d[32];
        TC_LD32(d, tmem + cb + g * 32);
        tc_wait_ld();
        uint32_t o[32];
#pragma unroll
        for (int j = 0; j < 32; j++) {
            int chl = cb + g * 32 + j;
            float vm = __uint_as_float(d[j]) + bsh[chl];
            float cached = sAT[(size_t)ridx[chl] * NTOK + blk * BM_ + tok];
            o[j] = f2tf(gelu_t(vm) - cached);
        }
        float* dp = g_delta + ((size_t)blk * BM_ + tok) * KSEL + mchunk * 128 + cb + g * 32;
#pragma unroll
        for (int q = 0; q < 8; q++) *(uint4*)(dp + q * 4) = *(uint4*)&o[q * 4];
    }
}
__device__ __forceinline__ void gemm2_epilogue(uint32_t tmem, const float* out_cache,
                                               float* out, int blk, int n0, int tid) {
    const int wid = tid >> 5, lane = tid & 31;
    const int subp = wid & 3, tok = subp * 32 + lane;
    const int cb = (wid >> 2) * 64;
#pragma unroll
    for (int g = 0; g < 2; g++) {
        uint32_t d[32];
        TC_LD32(d, tmem + cb + g * 32);
        tc_wait_ld();
        size_t off = (size_t)(blk * BM_ + tok) * C_DIM + n0 + cb + g * 32;
#pragma unroll
        for (int q = 0; q < 8; q++) {
            float4 oc = *(const float4*)(out_cache + off + q * 4);
            oc.x += __uint_as_float(d[q * 4 + 0]);
            oc.y += __uint_as_float(d[q * 4 + 1]);
            oc.z += __uint_as_float(d[q * 4 + 2]);
            oc.w += __uint_as_float(d[q * 4 + 3]);
            *(float4*)(out + off + q * 4) = oc;
        }
    }
}
#endif

// ---------------- kernel 4: gemm1 single-stage, reg prefetch (4 CTAs/SM) ----------------
__global__ __launch_bounds__(256, 4) void k_gemm1(const float* __restrict__ x,
                                                  const float* __restrict__ fc1w,
                                                  const float* __restrict__ fc1b,
                                                  const float* __restrict__ sAT) {
    extern __shared__ char dsm[];
    char* base = (char*)((((uintptr_t)dsm) + 1023) & ~(uintptr_t)1023);
    __shared__ int ridx[128];
    __shared__ float bsh[128];
    const int tid = threadIdx.x, wid = tid >> 5, lane = tid & 31;
    const int blk = blockIdx.y, mchunk = blockIdx.x;

#if TC_OK
    __shared__ uint32_t s_tmem;
    __shared__ uint64_t s_mbar;
    const uint32_t sb = sm32(base);

    if (wid == 0) { tc_alloc(sm32(&s_tmem), 128); tc_relinq(); }
    if (tid == 0) mbar_init(sm32(&s_mbar), 1);
    if (tid < 128) {
        int id = g_inds[blk * KSEL + mchunk * 128 + tid];
        ridx[tid] = id;
        bsh[tid] = fc1b[id];
    }
    __syncthreads();
    const uint32_t tmem = s_tmem;
    const uint32_t mb0 = sm32(&s_mbar);
    const uint32_t At = sb, Bt = sb + 16384;

    const float* xb = g_xr + (size_t)blk * BM_ * C_DIM;
    const int row = tid >> 3, c4 = tid & 7;
    float4 ra[4], rb[4];
#pragma unroll
    for (int r = 0; r < 4; r++) {
        int rr = row + 32 * r;
        ra[r] = *(const float4*)(xb + (size_t)rr * C_DIM + c4 * 4);
        rb[r] = *(const float4*)(fc1w + (size_t)ridx[rr] * C_DIM + c4 * 4);
    }
    const int NCH = C_DIM / 32;  // 96
    for (int i = 0; i < NCH; i++) {
        if (i >= 1) mbar_wait(mb0, (i - 1) & 1);
#pragma unroll
        for (int r = 0; r < 4; r++) {
            int rr = row + 32 * r;
            uint32_t off = SWZ(rr * 128 + c4 * 16);
            *(float4*)(base + off) = ra[r];             // At
            *(float4*)(base + 16384 + off) = rb[r];     // Bt
        }
        fence_async();
        if (i + 1 < NCH) {
            int k0 = (i + 1) * 32;
#pragma unroll
            for (int r = 0; r < 4; r++) {
                int rr = row + 32 * r;
                ra[r] = *(const float4*)(xb + (size_t)rr * C_DIM + k0 + c4 * 4);
                rb[r] = *(const float4*)(fc1w + (size_t)ridx[rr] * C_DIM + k0 + c4 * 4);
            }
        }
        __syncthreads();
        if (tid == 0) {
            uint64_t da = mk_desc(At), db = mk_desc(Bt);
#pragma unroll
            for (int ks = 0; ks < 4; ks++)
                mma_ss(tmem, da + ks * 2, db + ks * 2, (i | ks) ? 1u : 0u);
            tc_commit(mb0);
        }
    }
    mbar_wait(mb0, (NCH - 1) & 1);   // chunk 95: parity 1
    tc_fence_after();
    gemm1_epilogue(tmem, ridx, bsh, sAT, blk, mchunk, tid);
    __syncthreads();
    if (wid == 0) tc_dealloc(tmem, 128);

#else
    // fallback (dead on GB300): scalar-correct path
    (void)base; (void)wid; (void)lane;
    if (tid < 128) {
        int id = g_inds[blk * KSEL + mchunk * 128 + tid];
        ridx[tid] = id;
        bsh[tid] = fc1b[id];
    }
    __syncthreads();
    const float* xb = x + (size_t)blk * BM_ * C_DIM;
    for (int t = tid >> 1; t < 128; t += 128) {
        int half = tid & 1;
        for (int chl = half * 64; chl < half * 64 + 64; chl++) {
            const float* wr = fc1w + (size_t)ridx[chl] * C_DIM;
            const float* xr = xb + (size_t)t * C_DIM;
            float acc = 0.f;
            for (int k = 0; k < C_DIM; k++) acc += xr[k] * wr[k];
            float vm = acc + bsh[chl];
            float cached = sAT[(size_t)ridx[chl] * NTOK + blk * BM_ + t];
            g_delta[((size_t)blk * BM_ + t) * KSEL + mchunk * 128 + chl] = gelu_t(vm) - cached;
        }
    }
#endif
}

// ---------------- kernel 5: gemm2 single-stage, reg prefetch (4 CTAs/SM) ----------------
__global__ __launch_bounds__(256, 4) void k_gemm2(const float* __restrict__ fc2wT,
                                                  const float* __restrict__ out_cache,
                                                  float* __restrict__ out) {
    extern __shared__ char dsm[];
    char* base = (char*)((((uintptr_t)dsm) + 1023) & ~(uintptr_t)1023);
    __shared__ int kid[KSEL];
    const int tid = threadIdx.x, wid = tid >> 5, lane = tid & 31;
    const int blk = blockIdx.y, n0 = blockIdx.x * 128;

#if TC_OK
    __shared__ uint32_t s_tmem;
    __shared__ uint64_t s_mbar;
    const uint32_t sb = sm32(base);

    if (wid == 0) { tc_alloc(sm32(&s_tmem), 128); tc_relinq(); }
    if (tid == 0) mbar_init(sm32(&s_mbar), 1);
    for (int i = tid; i < KSEL; i += 256) kid[i] = g_inds[blk * KSEL + i];
    __syncthreads();
    const uint32_t tmem = s_tmem;
    const uint32_t mb0 = sm32(&s_mbar);
    const uint32_t At = sb, Bt = sb + 16384;

    const float* Ab = g_delta + (size_t)blk * BM_ * KSEL;
    const int row = tid >> 3, c4 = tid & 7;
    const int cB = tid & 127, ch4b = tid >> 7;   // B transpose mapping
    float4 ra[4];
    float rbv[4][4];
#pragma unroll
    for (int r = 0; r < 4; r++)
        ra[r] = *(const float4*)(Ab + (size_t)(row + 32 * r) * KSEL + c4 * 4);
#pragma unroll
    for (int j = 0; j < 4; j++) {
        int ch4 = ch4b + j * 2;
#pragma unroll
        for (int q = 0; q < 4; q++)
            rbv[j][q] = fc2wT[(size_t)kid[ch4 * 4 + q] * C_DIM + n0 + cB];
    }
    const int NCH = KSEL / 32;  // 48
    for (int i = 0; i < NCH; i++) {
        if (i >= 1) mbar_wait(mb0, (i - 1) & 1);
#pragma unroll
        for (int r = 0; r < 4; r++) {
            int rr = row + 32 * r;
            *(float4*)(base + SWZ(rr * 128 + c4 * 16)) = ra[r];
        }
#pragma unroll
        for (int j = 0; j < 4; j++) {
            int ch4 = ch4b + j * 2;
            *(float4*)(base + 16384 + SWZ(cB * 128 + ch4 * 16)) =
                make_float4(rbv[j][0], rbv[j][1], rbv[j][2], rbv[j][3]);
        }
        fence_async();
        if (i + 1 < NCH) {
            int k0 = (i + 1) * 32;
#pragma unroll
            for (int r = 0; r < 4; r++)
                ra[r] = *(const float4*)(Ab + (size_t)(row + 32 * r) * KSEL + k0 + c4 * 4);
#pragma unroll
            for (int j = 0; j < 4; j++) {
                int ch4 = ch4b + j * 2;
#pragma unroll
                for (int q = 0; q < 4; q++)
                    rbv[j][q] = fc2wT[(size_t)kid[k0 + ch4 * 4 + q] * C_DIM + n0 + cB];
            }
        }
        __syncthreads();
        if (tid == 0) {
            uint64_t da = mk_desc(At), db = mk_desc(Bt);
#pragma unroll
            for (int ks = 0; ks < 4; ks++)
                mma_ss(tmem, da + ks * 2, db + ks * 2, (i | ks) ? 1u : 0u);
            tc_commit(mb0);
        }
    }
    mbar_wait(mb0, (NCH - 1) & 1);   // chunk 47: parity 1
    tc_fence_after();
    gemm2_epilogue(tmem, out_cache, out, blk, n0, tid);
    __syncthreads();
    if (wid == 0) tc_dealloc(tmem, 128);

#else
    // fallback (dead on GB300): scalar-correct path
    (void)base; (void)wid; (void)lane;
    for (int i = tid; i < KSEL; i += 256) kid[i] = g_inds[blk * KSEL + i];
    __syncthreads();
    const float* Ab = g_delta + (size_t)blk * BM_ * KSEL;
    for (int t = tid >> 1; t < 128; t += 128) {
        int half = tid & 1;
        for (int c = half * 64; c < half * 64 + 64; c++) {
            float acc = 0.f;
            for (int k = 0; k < KSEL; k++)
                acc += Ab[(size_t)t * KSEL + k] * fc2wT[(size_t)kid[k] * C_DIM + n0 + c];
            size_t off = (size_t)(blk * BM_ + t) * C_DIM + n0 + c;
            out[off] = out_cache[off] + acc;
        }
    }
#endif
}

// ---------------- launch (serial) ----------------
extern "C" void kernel_launch(void* const* d_in, const int* in_sizes, int n_in,
                              void* d_out, int out_size) {
    const float* x     = (const float*)d_in[0];
    const float* fc1w  = (const float*)d_in[1];
    const float* fc1b  = (const float*)d_in[2];
    const float* fc2wT = (const float*)d_in[3];
    const float* bmc   = (const float*)d_in[4];
    const float* sAT   = (const float*)d_in[5];
    const float* outc  = (const float*)d_in[6];
    float* out = (float*)d_out;

    cudaFuncSetAttribute(k_sel,   cudaFuncAttributeMaxDynamicSharedMemorySize, SEL_SMEM);
    cudaFuncSetAttribute(k_gemm1, cudaFuncAttributeMaxDynamicSharedMemorySize, G_SMEM);
    cudaFuncSetAttribute(k_gemm2, cudaFuncAttributeMaxDynamicSharedMemorySize, G_SMEM);

    k_xr<<<NTOK * C_DIM / 1024, 256>>>(x);
    k_bmean<<<dim3(256, 6), 512>>>(x);
    k_sel<<<dim3(96, 2), 256, SEL_SMEM>>>(fc1w, fc1b, bmc);
    k_topk<<<32, 1024>>>();
    k_gemm1<<<dim3(12, 32), 256, G_SMEM>>>(x, fc1w, fc1b, sAT);
    k_gemm2<<<dim3(24, 32), 256, G_SMEM>>>(fc2wT, outc, out);
}